// round 14
// baseline (speedup 1.0000x reference)
#include <cuda_runtime.h>
#include <cuda_fp16.h>
#include <cstdint>

typedef unsigned long long u64;
typedef unsigned int u32;
#define CEPS 1e-5f

// ===================== helpers =====================
__device__ __forceinline__ u32 smem_u32(const void* p) {
    u32 a;
    asm("{ .reg .u64 t; cvta.to.shared.u64 t, %1; cvt.u32.u64 %0, t; }" : "=r"(a) : "l"(p));
    return a;
}
#define SWZ128(o) ((o) ^ (((o) >> 3) & 0x70))

__device__ __forceinline__ void ldsm4(u32& r0, u32& r1, u32& r2, u32& r3, u32 addr) {
    asm volatile("ldmatrix.sync.aligned.m8n8.x4.shared.b16 {%0,%1,%2,%3}, [%4];"
        : "=r"(r0), "=r"(r1), "=r"(r2), "=r"(r3) : "r"(addr));
}
__device__ __forceinline__ void mma16816(float* c, const u32* a, const u32* b) {
    asm volatile("mma.sync.aligned.m16n8k16.row.col.f32.f16.f16.f32 "
        "{%0,%1,%2,%3}, {%4,%5,%6,%7}, {%8,%9}, {%0,%1,%2,%3};"
        : "+f"(c[0]), "+f"(c[1]), "+f"(c[2]), "+f"(c[3])
        : "r"(a[0]), "r"(a[1]), "r"(a[2]), "r"(a[3]), "r"(b[0]), "r"(b[1]));
}
__device__ __forceinline__ void cpa16(u32 dst, const void* src) {
    asm volatile("cp.async.cg.shared.global [%0], [%1], 16;" :: "r"(dst), "l"(src));
}
__device__ __forceinline__ void cpa16z(u32 dst, const void* src, bool ok) {
    u32 sz = ok ? 16u : 0u;
    asm volatile("cp.async.cg.shared.global [%0], [%1], 16, %2;" :: "r"(dst), "l"(src), "r"(sz));
}
#define CP_COMMIT() asm volatile("cp.async.commit_group;" ::: "memory")
#define CP_WAIT(n)  asm volatile("cp.async.wait_group %0;" :: "n"(n) : "memory")

__device__ __forceinline__ u32 h2_u32(float a, float b) {
    __half2 h = __floats2half2_rn(a, b);
    return *reinterpret_cast<u32*>(&h);
}

// ===================== device scratch =====================
__device__ __half d_imTh[8 * 256 * 2048];         // [b][hw][cin] fp16
__device__ __half d_pwH[1024 * 2048];             // proj_w fp16
__device__ __half d_xh[8 * 256 * 1024];           // projected feats fp16
__device__ float d_tb[256];
__device__ __half d_Rh[512ull * 49 * 1024];       // roi feats fp16
__device__ __half d_Wc[256ull * 9216];            // conv w fp16 [o][t*1024+ci]
__device__ float d_cvp[2ull * 25088 * 256];       // conv split-K partials f32
__device__ __half d_r1h[512ull * 12544];          // conv out fp16, K order p*256+o
__device__ __half d_fcWh[1024ull * 12544];        // fc w fp16, K reordered
__device__ float d_fcp[14ull * 512 * 1024];       // FC split-K partials
__device__ __half d_featsH[512 * 1280];           // LN'd features fp16
__device__ __half d_g1H[2560 * 1280];             // g1 rearranged: [U rows | V rows][1280]
__device__ float d_g1b2[2560];                    // [g1_b | zeros]
__device__ __half d_UVh[512 * 2560];              // [row][U'(+bias) 1280 | V 1280] fp16
__device__ __half d_h2h[32768ull * 1280];
__device__ __half d_w2h[1280ull * 1280];
__device__ __half d_w3h[1280ull * 1280];
__device__ float d_gp[256 * 1280];

// ===================== prep kernels =====================
__global__ void transpose_bchw_h(const float* __restrict__ in, __half* __restrict__ out) {
    __shared__ float tile[32][33];
    int b = blockIdx.z, p0 = blockIdx.x * 32, c0 = blockIdx.y * 32;
    int tx = threadIdx.x, ty = threadIdx.y;
    const float* ip = in + (long long)b * 2048 * 256;
    #pragma unroll
    for (int i = 0; i < 32; i += 8) tile[ty + i][tx] = ip[(c0 + ty + i) * 256 + p0 + tx];
    __syncthreads();
    __half* op = out + (long long)b * 256 * 2048;
    #pragma unroll
    for (int i = 0; i < 32; i += 8)
        op[(p0 + ty + i) * 2048 + c0 + tx] = __float2half_rn(tile[tx][ty + i]);
}

__global__ void conv_f2h(const float* __restrict__ in, __half* __restrict__ out, int n) {
    int i = blockIdx.x * 256 + threadIdx.x;
    if (i < n) out[i] = __float2half_rn(in[i]);
}

// g1_w [1280][2560] -> g1H [2560][1280]: row n<1280 = g1a (U), n>=1280 = g1b (V)
__global__ void prep_g1(const float* __restrict__ w, __half* __restrict__ o) {
    int i = blockIdx.x * 256 + threadIdx.x;   // < 2560*1280
    int n = i / 1280, k = i - n * 1280;
    int srcRow = (n >= 1280) ? (n - 1280) : n;
    int srcCol = ((n >= 1280) ? 1280 : 0) + k;
    o[i] = __float2half_rn(w[(size_t)srcRow * 2560 + srcCol]);
}

__global__ void prep_g1b(const float* __restrict__ g1b, float* __restrict__ o) {
    int i = blockIdx.x * 256 + threadIdx.x;   // < 2560
    o[i] = (i < 1280) ? g1b[i] : 0.f;
}

__global__ void prep_convw_fp16(const float* __restrict__ cw, const float* __restrict__ g,
                                const float* __restrict__ vv, __half* __restrict__ Wc) {
    __shared__ float sf[9216];
    int o = blockIdx.x;
    for (int j = threadIdx.x; j < 9216; j += 256) sf[j] = cw[o * 9216 + j];   // [ci][t]
    __syncthreads();
    float s = g[o] * rsqrtf(vv[o] + CEPS);
    for (int r = threadIdx.x; r < 9216; r += 256) {
        int t = r >> 10, ci = r & 1023;
        Wc[(size_t)o * 9216 + r] = __float2half_rn(sf[ci * 9 + t] * s);
    }
}

__global__ void prep_tb(const float* __restrict__ cb, const float* __restrict__ g,
                        const float* __restrict__ b, const float* __restrict__ m,
                        const float* __restrict__ v, float* __restrict__ tb) {
    int o = threadIdx.x;
    float s = g[o] * rsqrtf(v[o] + CEPS);
    tb[o] = (cb[o] - m[o]) * s + b[o];
}

__global__ void prep_fcw(const float* __restrict__ fw, __half* __restrict__ o) {
    extern __shared__ float sf[];   // 12544 floats
    int n = blockIdx.x;
    for (int j = threadIdx.x; j < 12544; j += 256) sf[j] = fw[n * 12544 + j];
    __syncthreads();
    for (int j = threadIdx.x; j < 12544; j += 256) {
        int p = j >> 8, oo = j & 255;
        o[(size_t)n * 12544 + j] = __float2half_rn(sf[oo * 49 + p]);
    }
}

// conv split-K reduce: r1h = relu(P0 + P1 + tb)
__global__ void conv_reduce(const float* __restrict__ P, const float* __restrict__ tb,
                            __half* __restrict__ r1h) {
    int i = blockIdx.x * 256 + threadIdx.x;   // over 25088*256/2 pairs
    int e = i * 2;
    float2 a = *(const float2*)(P + e);
    float2 b = *(const float2*)(P + 25088ull * 256 + e);
    int col = e & 255;
    float v0 = fmaxf(a.x + b.x + tb[col], 0.f);
    float v1 = fmaxf(a.y + b.y + tb[col + 1], 0.f);
    *(u32*)(r1h + e) = h2_u32(v0, v1);
}

// ===================== HMMA GEMM: pure fp16, fp32 accum ====================
// 128x128 tile, 8 warps (2M x 4N, 64x32 each), K chunks of 64,
// 2-stage cp.async double buffer.
// MODE 0: g2 (A tile built on the fly: relu(U'+V) from UVh)
// MODE 1: g3   MODE 3: FC   MODE 4: proj   MODE 5: UV (+bias, fp16, ldc 2560)
// MODE 6: conv split-K (z over 2 halves of 144 chunks), raw f32 partials
template<int MODE>
__global__ void __launch_bounds__(256, 2) hgemm(
    const __half* __restrict__ A, const __half* __restrict__ B,
    const float* __restrict__ bias,
    __half* __restrict__ outH, float* __restrict__ outF,
    int nkin, int lda, int ldb)
{
    extern __shared__ char dsm[];
    const u32 raw = smem_u32(dsm);
    const u32 base = (raw + 1023u) & ~1023u;
    char* smem_g = dsm + (base - raw);

    const int tid = threadIdx.x;
    const int lane = tid & 31;
    const int w = tid >> 5;
    const int wM = w >> 2, wN = w & 3;
    const int nB = blockIdx.x * 128, mB = blockIdx.y * 128;
    const int kinBase = (MODE == 3 || MODE == 6) ? blockIdx.z * nkin : 0;

    const int lrow = tid >> 3, lc16 = tid & 7;

    int cn4[4], cy4[4], cx4[4];
    if (MODE == 6) {
        #pragma unroll
        for (int p = 0; p < 4; p++) {
            int r = mB + p * 32 + lrow;
            int n = r / 49, pp = r - n * 49;
            cn4[p] = n; cy4[p] = pp / 7; cx4[p] = pp - (pp / 7) * 7;
        }
    }
    int ru[4], rv[4];
    if (MODE == 0) {
        #pragma unroll
        for (int p = 0; p < 4; p++) {
            int row = mB + p * 32 + lrow;
            int img = row >> 12, a = (row >> 6) & 63, b = row & 63;
            ru[p] = img * 64 + b;
            rv[p] = img * 64 + a;
        }
    }

    u32 soff[4];
    #pragma unroll
    for (int p = 0; p < 4; p++) {
        u32 off = (u32)(((p * 32 + lrow) << 7) | (lc16 << 4));
        soff[p] = SWZ128(off);
    }

    auto gload = [&](int c, int s) {
        int kin = kinBase + c;
        u32 sg = base + (u32)s * 32768u;
        char* sgp = smem_g + (size_t)s * 32768u;
        int kOff = (kin << 6) + (lc16 << 3);
        if (MODE == 6) {
            int t = kin >> 4, ci0 = (kin & 15) << 6;
            int dy = t / 3 - 1, dx = t - (t / 3) * 3 - 1;
            #pragma unroll
            for (int p = 0; p < 4; p++) {
                int iy = cy4[p] + dy, ix = cx4[p] + dx;
                bool ok = (iy >= 0) && (iy < 7) && (ix >= 0) && (ix < 7);
                const __half* src = ok ?
                    (A + (((size_t)(cn4[p] * 49 + iy * 7 + ix)) << 10) + ci0 + (lc16 << 3)) : A;
                cpa16z(sg + soff[p], src, ok);
            }
        } else if (MODE == 0) {
            const __half2 z2 = __float2half2_rn(0.f);
            #pragma unroll
            for (int p = 0; p < 4; p++) {
                uint4 uv = *(const uint4*)(A + (size_t)ru[p] * 2560 + kOff);
                uint4 vv = *(const uint4*)(A + (size_t)rv[p] * 2560 + 1280 + kOff);
                const __half2* u2 = (const __half2*)&uv;
                const __half2* v2 = (const __half2*)&vv;
                uint4 r;
                __half2* r2 = (__half2*)&r;
                #pragma unroll
                for (int q = 0; q < 4; q++) r2[q] = __hmax2(__hadd2(u2[q], v2[q]), z2);
                *(uint4*)(sgp + soff[p]) = r;
            }
        } else {
            #pragma unroll
            for (int p = 0; p < 4; p++)
                cpa16(sg + soff[p], A + (size_t)(mB + p * 32 + lrow) * lda + kOff);
        }
        #pragma unroll
        for (int p = 0; p < 4; p++)
            cpa16(sg + 16384u + soff[p], B + (size_t)(nB + p * 32 + lrow) * ldb + kOff);
    };

    float acc[4][4][4];
    #pragma unroll
    for (int mi = 0; mi < 4; mi++)
        #pragma unroll
        for (int ni = 0; ni < 4; ni++)
            #pragma unroll
            for (int r = 0; r < 4; r++) acc[mi][ni][r] = 0.f;

    const u32 aRow = (u32)(wM * 64 + (lane & 15));
    const u32 aSegX = (lane & 16) ? 16u : 0u;
    const u32 bRow = (u32)(wN * 32 + (lane & 7) + ((lane & 16) ? 8 : 0));
    const u32 bSegX = (lane & 8) ? 16u : 0u;

    gload(0, 0); CP_COMMIT();
    if (nkin > 1) { gload(1, 1); CP_COMMIT(); }

    for (int c = 0; c < nkin; c++) {
        int s = c & 1;
        if (c + 1 < nkin) { CP_WAIT(1); } else { CP_WAIT(0); }
        __syncthreads();
        u32 aBase = base + (u32)s * 32768u;
        u32 bB = aBase + 16384u;
        #pragma unroll
        for (int ks = 0; ks < 4; ks++) {
            u32 kb = (u32)(ks * 32);
            u32 afr[4][4];
            #pragma unroll
            for (int mi = 0; mi < 4; mi++)
                ldsm4(afr[mi][0], afr[mi][1], afr[mi][2], afr[mi][3],
                      aBase + SWZ128(((aRow + mi * 16) << 7) + kb + aSegX));
            u32 bfr[4][2];
            #pragma unroll
            for (int q = 0; q < 2; q++) {
                u32 r0, r1, r2, r3;
                ldsm4(r0, r1, r2, r3, bB + SWZ128(((bRow + q * 16) << 7) + kb + bSegX));
                bfr[2 * q][0] = r0; bfr[2 * q][1] = r1;
                bfr[2 * q + 1][0] = r2; bfr[2 * q + 1][1] = r3;
            }
            #pragma unroll
            for (int mi = 0; mi < 4; mi++)
                #pragma unroll
                for (int ni = 0; ni < 4; ni++)
                    mma16816(acc[mi][ni], afr[mi], bfr[ni]);
        }
        __syncthreads();
        if (c + 2 < nkin) { gload(c + 2, s); CP_COMMIT(); }
    }

    // ---------------- epilogue ----------------
    const int gRow0 = mB + wM * 64 + (lane >> 2);
    const int gCol0 = nB + wN * 32 + (lane & 3) * 2;

    if (MODE == 0) {
        #pragma unroll
        for (int mi = 0; mi < 4; mi++)
            #pragma unroll
            for (int rg = 0; rg < 2; rg++) {
                int row = gRow0 + mi * 16 + rg * 8;
                #pragma unroll
                for (int ni = 0; ni < 4; ni++) {
                    int col = gCol0 + ni * 8;
                    float v0 = fmaxf(acc[mi][ni][rg * 2] + bias[col], 0.f);
                    float v1 = fmaxf(acc[mi][ni][rg * 2 + 1] + bias[col + 1], 0.f);
                    *(u32*)(outH + (size_t)row * 1280 + col) = h2_u32(v0, v1);
                }
            }
    } else if (MODE == 1) {
        float s0[4], s1[4];
        #pragma unroll
        for (int ni = 0; ni < 4; ni++) {
            int col = gCol0 + ni * 8;
            float b0 = bias[col], b1 = bias[col + 1];
            float t0 = 0.f, t1 = 0.f;
            #pragma unroll
            for (int mi = 0; mi < 4; mi++) {
                t0 += fmaxf(acc[mi][ni][0] + b0, 0.f) + fmaxf(acc[mi][ni][2] + b0, 0.f);
                t1 += fmaxf(acc[mi][ni][1] + b1, 0.f) + fmaxf(acc[mi][ni][3] + b1, 0.f);
            }
            #pragma unroll
            for (int m = 4; m < 32; m <<= 1) {
                t0 += __shfl_xor_sync(0xffffffffu, t0, m);
                t1 += __shfl_xor_sync(0xffffffffu, t1, m);
            }
            s0[ni] = t0; s1[ni] = t1;
        }
        float* CS = (float*)dsm;
        __syncthreads();
        if (lane < 4) {
            #pragma unroll
            for (int ni = 0; ni < 4; ni++) {
                int colL = wN * 32 + ni * 8 + lane * 2;
                CS[wM * 128 + colL] = s0[ni];
                CS[wM * 128 + colL + 1] = s1[ni];
            }
        }
        __syncthreads();
        if (tid < 128)
            outF[(size_t)blockIdx.y * 1280 + nB + tid] = CS[tid] + CS[128 + tid];
    } else if (MODE == 3) {
        float* Fout = outF + (size_t)blockIdx.z * 512 * 1024;
        #pragma unroll
        for (int mi = 0; mi < 4; mi++)
            #pragma unroll
            for (int rg = 0; rg < 2; rg++) {
                int row = gRow0 + mi * 16 + rg * 8;
                #pragma unroll
                for (int ni = 0; ni < 4; ni++) {
                    int col = gCol0 + ni * 8;
                    *(float2*)(Fout + (size_t)row * 1024 + col) =
                        make_float2(acc[mi][ni][rg * 2], acc[mi][ni][rg * 2 + 1]);
                }
            }
    } else if (MODE == 4) {
        #pragma unroll
        for (int mi = 0; mi < 4; mi++)
            #pragma unroll
            for (int rg = 0; rg < 2; rg++) {
                int row = gRow0 + mi * 16 + rg * 8;
                #pragma unroll
                for (int ni = 0; ni < 4; ni++) {
                    int col = gCol0 + ni * 8;
                    float v0 = acc[mi][ni][rg * 2] + bias[col];
                    float v1 = acc[mi][ni][rg * 2 + 1] + bias[col + 1];
                    *(u32*)(outH + (size_t)row * 1024 + col) = h2_u32(v0, v1);
                }
            }
    } else if (MODE == 5) {
        #pragma unroll
        for (int mi = 0; mi < 4; mi++)
            #pragma unroll
            for (int rg = 0; rg < 2; rg++) {
                int row = gRow0 + mi * 16 + rg * 8;
                #pragma unroll
                for (int ni = 0; ni < 4; ni++) {
                    int col = gCol0 + ni * 8;
                    float v0 = acc[mi][ni][rg * 2] + bias[col];
                    float v1 = acc[mi][ni][rg * 2 + 1] + bias[col + 1];
                    *(u32*)(outH + (size_t)row * 2560 + col) = h2_u32(v0, v1);
                }
            }
    } else {   // MODE 6: conv partials raw f32, ldc 256
        float* Fout = outF + (size_t)blockIdx.z * 25088 * 256;
        #pragma unroll
        for (int mi = 0; mi < 4; mi++)
            #pragma unroll
            for (int rg = 0; rg < 2; rg++) {
                int row = gRow0 + mi * 16 + rg * 8;
                #pragma unroll
                for (int ni = 0; ni < 4; ni++) {
                    int col = gCol0 + ni * 8;
                    *(float2*)(Fout + (size_t)row * 256 + col) =
                        make_float2(acc[mi][ni][rg * 2], acc[mi][ni][rg * 2 + 1]);
                }
            }
    }
}

// ===================== ROIAlign (fp16 in/out) =====================
__global__ void roialign_fp16(const __half* __restrict__ x, const float* __restrict__ boxes,
                              __half* __restrict__ oh)
{
    int blk = blockIdx.x;     // 0..25087
    int n = blk / 49;
    int bin = blk - n * 49;
    int by = bin / 7, bx = bin - by * 7;
    int b = n >> 6;
    const float* roi = boxes + n * 4;
    float x1 = roi[0] * (1.f / 32.f) - 0.5f;
    float y1 = roi[1] * (1.f / 32.f) - 0.5f;
    float bw = (roi[2] - roi[0]) * (1.f / 32.f) * (1.f / 7.f);
    float bh = (roi[3] - roi[1]) * (1.f / 32.f) * (1.f / 7.f);
    int pidx[16];
    float pw[16];
    int cnt = 0;
    #pragma unroll
    for (int sy = 0; sy < 2; sy++) {
        float ys = y1 + bh * ((float)by + (sy + 0.5f) * 0.5f);
        bool vy = (ys >= -1.f) && (ys <= 16.f);
        float v = fmaxf(ys, 0.f);
        int lo = (int)floorf(v);
        int yl, yh; float wy;
        if (lo >= 15) { yl = 15; yh = 15; wy = 0.f; }
        else { yl = lo; yh = lo + 1; wy = v - (float)lo; }
        #pragma unroll
        for (int sx = 0; sx < 2; sx++) {
            float xs = x1 + bw * ((float)bx + (sx + 0.5f) * 0.5f);
            bool vx = (xs >= -1.f) && (xs <= 16.f);
            float u = fmaxf(xs, 0.f);
            int lo2 = (int)floorf(u);
            int xl, xh; float wx;
            if (lo2 >= 15) { xl = 15; xh = 15; wx = 0.f; }
            else { xl = lo2; xh = lo2 + 1; wx = u - (float)lo2; }
            float m = (vy && vx) ? 0.25f : 0.f;
            pidx[cnt] = yl * 16 + xl; pw[cnt] = (1.f - wy) * (1.f - wx) * m; cnt++;
            pidx[cnt] = yl * 16 + xh; pw[cnt] = (1.f - wy) * wx * m;         cnt++;
            pidx[cnt] = yh * 16 + xl; pw[cnt] = wy * (1.f - wx) * m;         cnt++;
            pidx[cnt] = yh * 16 + xh; pw[cnt] = wy * wx * m;                 cnt++;
        }
    }
    const __half* xb = x + ((long long)b << 18);
    int c = threadIdx.x * 4;
    float acc0 = 0.f, acc1 = 0.f, acc2 = 0.f, acc3 = 0.f;
    #pragma unroll
    for (int t = 0; t < 16; t++) {
        uint2 hv = *(const uint2*)(xb + (pidx[t] << 10) + c);
        float2 f0 = __half22float2(*reinterpret_cast<__half2*>(&hv.x));
        float2 f1 = __half22float2(*reinterpret_cast<__half2*>(&hv.y));
        acc0 += pw[t] * f0.x; acc1 += pw[t] * f0.y;
        acc2 += pw[t] * f1.x; acc3 += pw[t] * f1.y;
    }
    size_t o = ((size_t)blk << 10) + c;
    *(uint2*)(oh + o) = make_uint2(h2_u32(acc0, acc1), h2_u32(acc2, acc3));
}

// ===================== FC reduce + LN1 (fp16 out) =====================
__global__ void fc_reduce_ln(const float* __restrict__ part, const float* __restrict__ fcb,
                             const float* __restrict__ g, const float* __restrict__ b,
                             __half* __restrict__ featsH)
{
    __shared__ float sv[1024];
    __shared__ float red[256];
    int n = blockIdx.x, tid = threadIdx.x;
    float s = 0.f;
    #pragma unroll
    for (int i = 0; i < 4; i++) {
        int col = i * 256 + tid;
        float v = fcb[col];
        #pragma unroll
        for (int z = 0; z < 14; z++) v += part[(long long)((z << 9) + n) * 1024 + col];
        v = fmaxf(v, 0.f);
        sv[col] = v;
        s += v;
    }
    red[tid] = s; __syncthreads();
    for (int st = 128; st > 0; st >>= 1) { if (tid < st) red[tid] += red[tid + st]; __syncthreads(); }
    float mu = red[0] * (1.f / 1024.f);
    __syncthreads();
    float q = 0.f;
    #pragma unroll
    for (int i = 0; i < 4; i++) { float d = sv[i * 256 + tid] - mu; q += d * d; }
    red[tid] = q; __syncthreads();
    for (int st = 128; st > 0; st >>= 1) { if (tid < st) red[tid] += red[tid + st]; __syncthreads(); }
    float rstd = rsqrtf(red[0] * (1.f / 1024.f) + CEPS);
    #pragma unroll
    for (int i = 0; i < 4; i++) {
        int col = i * 256 + tid;
        featsH[(long long)n * 1280 + col] =
            __float2half_rn((sv[col] - mu) * rstd * g[col] + b[col]);
    }
}

// ===================== box branch (fp16 out) =====================
__global__ void box_ln(const float* __restrict__ nbx, const float* __restrict__ bw,
                       const float* __restrict__ bb, const float* __restrict__ g,
                       const float* __restrict__ be, __half* __restrict__ featsH)
{
    __shared__ float red[256];
    int n = blockIdx.x, tid = threadIdx.x;
    float a0 = nbx[n * 4 + 0] * 2.f - 1.f;
    float a1 = nbx[n * 4 + 1] * 2.f - 1.f;
    float a2 = nbx[n * 4 + 2] * 2.f - 1.f;
    float a3 = nbx[n * 4 + 3] * 2.f - 1.f;
    const float* w = bw + tid * 4;
    float v = w[0] * a0 + w[1] * a1 + w[2] * a2 + w[3] * a3 + bb[tid];
    red[tid] = v; __syncthreads();
    for (int st = 128; st > 0; st >>= 1) { if (tid < st) red[tid] += red[tid + st]; __syncthreads(); }
    float mu = red[0] * (1.f / 256.f);
    __syncthreads();
    float d = v - mu;
    red[tid] = d * d; __syncthreads();
    for (int st = 128; st > 0; st >>= 1) { if (tid < st) red[tid] += red[tid + st]; __syncthreads(); }
    float rstd = rsqrtf(red[0] * (1.f / 256.f) + CEPS);
    featsH[(long long)n * 1280 + 1024 + tid] =
        __float2half_rn((v - mu) * rstd * g[tid] + be[tid]);
}

// ===================== final reduce =====================
__global__ void final_reduce(const float* __restrict__ gp, float* __restrict__ out)
{
    int i = blockIdx.x * 256 + threadIdx.x;   // < 10240
    int img = i / 1280, j = i - img * 1280;
    float s = 0.f;
    #pragma unroll
    for (int mb = 0; mb < 32; mb++)
        s += gp[(long long)(img * 32 + mb) * 1280 + j];
    out[i] = s;
}

// ===================== launch =====================
extern "C" void kernel_launch(void* const* d_in, const int* in_sizes, int n_in,
                              void* d_out, int out_size)
{
    const float* im_feat = (const float*)d_in[0];
    const float* boxes   = (const float*)d_in[1];
    const float* nboxes  = (const float*)d_in[2];
    const float* proj_w  = (const float*)d_in[3];
    const float* proj_b  = (const float*)d_in[4];
    const float* conv_w  = (const float*)d_in[5];
    const float* conv_b  = (const float*)d_in[6];
    const float* bn_g = (const float*)d_in[7];
    const float* bn_b = (const float*)d_in[8];
    const float* bn_m = (const float*)d_in[9];
    const float* bn_v = (const float*)d_in[10];
    const float* fc_w = (const float*)d_in[11];
    const float* fc_b = (const float*)d_in[12];
    const float* ln1_g = (const float*)d_in[13];
    const float* ln1_b = (const float*)d_in[14];
    const float* box_w = (const float*)d_in[15];
    const float* box_b = (const float*)d_in[16];
    const float* ln2_g = (const float*)d_in[17];
    const float* ln2_b = (const float*)d_in[18];
    const float* g1_w = (const float*)d_in[19];
    const float* g1_b = (const float*)d_in[20];
    const float* g2_w = (const float*)d_in[21];
    const float* g2_b = (const float*)d_in[22];
    const float* g3_w = (const float*)d_in[23];
    const float* g3_b = (const float*)d_in[24];
    float* out = (float*)d_out;

    float *p_tb, *p_cvp, *p_fcp, *p_g1b2, *p_gp;
    __half *p_imTh, *p_pwH, *p_xh, *p_Rh, *p_Wc, *p_r1h, *p_fcWh, *p_featsH, *p_g1H,
           *p_UVh, *p_h2h, *p_w2h, *p_w3h;
    cudaGetSymbolAddress((void**)&p_imTh, d_imTh);
    cudaGetSymbolAddress((void**)&p_pwH, d_pwH);
    cudaGetSymbolAddress((void**)&p_xh, d_xh);
    cudaGetSymbolAddress((void**)&p_tb, d_tb);
    cudaGetSymbolAddress((void**)&p_cvp, d_cvp);
    cudaGetSymbolAddress((void**)&p_fcp, d_fcp);
    cudaGetSymbolAddress((void**)&p_featsH, d_featsH);
    cudaGetSymbolAddress((void**)&p_g1H, d_g1H);
    cudaGetSymbolAddress((void**)&p_g1b2, d_g1b2);
    cudaGetSymbolAddress((void**)&p_UVh, d_UVh);
    cudaGetSymbolAddress((void**)&p_gp, d_gp);
    cudaGetSymbolAddress((void**)&p_Rh, d_Rh);
    cudaGetSymbolAddress((void**)&p_Wc, d_Wc);
    cudaGetSymbolAddress((void**)&p_r1h, d_r1h);
    cudaGetSymbolAddress((void**)&p_fcWh, d_fcWh);
    cudaGetSymbolAddress((void**)&p_h2h, d_h2h);
    cudaGetSymbolAddress((void**)&p_w2h, d_w2h);
    cudaGetSymbolAddress((void**)&p_w3h, d_w3h);

    const int SMEMSZ = 2 * 32768 + 1024;   // 66560
    cudaFuncSetAttribute(hgemm<0>, cudaFuncAttributeMaxDynamicSharedMemorySize, SMEMSZ);
    cudaFuncSetAttribute(hgemm<1>, cudaFuncAttributeMaxDynamicSharedMemorySize, SMEMSZ);
    cudaFuncSetAttribute(hgemm<3>, cudaFuncAttributeMaxDynamicSharedMemorySize, SMEMSZ);
    cudaFuncSetAttribute(hgemm<4>, cudaFuncAttributeMaxDynamicSharedMemorySize, SMEMSZ);
    cudaFuncSetAttribute(hgemm<5>, cudaFuncAttributeMaxDynamicSharedMemorySize, SMEMSZ);
    cudaFuncSetAttribute(hgemm<6>, cudaFuncAttributeMaxDynamicSharedMemorySize, SMEMSZ);
    cudaFuncSetAttribute(prep_fcw, cudaFuncAttributeMaxDynamicSharedMemorySize, 50176);

    // launches ordered so #4 = proj hgemm
    transpose_bchw_h<<<dim3(8, 64, 8), dim3(32, 8)>>>(im_feat, p_imTh);          // 1
    conv_f2h<<<8192, 256>>>(proj_w, p_pwH, 1024 * 2048);                          // 2
    prep_tb<<<1, 256>>>(conv_b, bn_g, bn_b, bn_m, bn_v, p_tb);                    // 3
    hgemm<4><<<dim3(8, 16), 256, SMEMSZ>>>(p_imTh, p_pwH, proj_b, p_xh, nullptr,  // 4
                                           32, 2048, 2048);
    roialign_fp16<<<25088, 256>>>(p_xh, boxes, p_Rh);                             // 5
    prep_convw_fp16<<<256, 256>>>(conv_w, bn_g, bn_v, p_Wc);                      // 6
    // conv split-K=2 (z over 72-chunk halves) -> f32 partials
    hgemm<6><<<dim3(2, 196, 2), 256, SMEMSZ>>>(p_Rh, p_Wc, nullptr, nullptr,      // 7
                                               p_cvp, 72, 0, 9216);
    conv_reduce<<<12544, 256>>>(p_cvp, p_tb, p_r1h);                              // 8
    prep_fcw<<<1024, 256, 50176>>>(fc_w, p_fcWh);                                 // 9
    hgemm<3><<<dim3(8, 4, 14), 256, SMEMSZ>>>(p_r1h, p_fcWh, nullptr, nullptr,    // 10
                                              p_fcp, 14, 12544, 12544);
    fc_reduce_ln<<<512, 256>>>(p_fcp, fc_b, ln1_g, ln1_b, p_featsH);              // 11
    box_ln<<<512, 256>>>(nboxes, box_w, box_b, ln2_g, ln2_b, p_featsH);           // 12
    prep_g1<<<12800, 256>>>(g1_w, p_g1H);                                         // 13
    prep_g1b<<<10, 256>>>(g1_b, p_g1b2);                                          // 14
    hgemm<5><<<dim3(20, 4), 256, SMEMSZ>>>(p_featsH, p_g1H, p_g1b2, p_UVh,        // 15
                                           nullptr, 20, 1280, 1280);
    conv_f2h<<<6400, 256>>>(g2_w, p_w2h, 1280 * 1280);                            // 16
    // g2 with fused h1 build (A = UVh)
    hgemm<0><<<dim3(10, 256), 256, SMEMSZ>>>(p_UVh, p_w2h, g2_b, p_h2h, nullptr,  // 17
                                             20, 2560, 1280);
    conv_f2h<<<6400, 256>>>(g3_w, p_w3h, 1280 * 1280);                            // 18
    hgemm<1><<<dim3(10, 256), 256, SMEMSZ>>>(p_h2h, p_w3h, g3_b, nullptr, p_gp,   // 19
                                             20, 1280, 1280);
    final_reduce<<<40, 256>>>(p_gp, out);                                         // 20
}

// round 15
// speedup vs baseline: 1.0039x; 1.0039x over previous
#include <cuda_runtime.h>
#include <cuda_fp16.h>
#include <cstdint>

typedef unsigned long long u64;
typedef unsigned int u32;
#define CEPS 1e-5f

// ===================== helpers =====================
__device__ __forceinline__ u32 smem_u32(const void* p) {
    u32 a;
    asm("{ .reg .u64 t; cvta.to.shared.u64 t, %1; cvt.u32.u64 %0, t; }" : "=r"(a) : "l"(p));
    return a;
}
#define SWZ128(o) ((o) ^ (((o) >> 3) & 0x70))

__device__ __forceinline__ void ldsm4(u32& r0, u32& r1, u32& r2, u32& r3, u32 addr) {
    asm volatile("ldmatrix.sync.aligned.m8n8.x4.shared.b16 {%0,%1,%2,%3}, [%4];"
        : "=r"(r0), "=r"(r1), "=r"(r2), "=r"(r3) : "r"(addr));
}
__device__ __forceinline__ void mma16816(float* c, const u32* a, const u32* b) {
    asm volatile("mma.sync.aligned.m16n8k16.row.col.f32.f16.f16.f32 "
        "{%0,%1,%2,%3}, {%4,%5,%6,%7}, {%8,%9}, {%0,%1,%2,%3};"
        : "+f"(c[0]), "+f"(c[1]), "+f"(c[2]), "+f"(c[3])
        : "r"(a[0]), "r"(a[1]), "r"(a[2]), "r"(a[3]), "r"(b[0]), "r"(b[1]));
}
__device__ __forceinline__ void cpa16(u32 dst, const void* src) {
    asm volatile("cp.async.cg.shared.global [%0], [%1], 16;" :: "r"(dst), "l"(src));
}
__device__ __forceinline__ void cpa16z(u32 dst, const void* src, bool ok) {
    u32 sz = ok ? 16u : 0u;
    asm volatile("cp.async.cg.shared.global [%0], [%1], 16, %2;" :: "r"(dst), "l"(src), "r"(sz));
}
#define CP_COMMIT() asm volatile("cp.async.commit_group;" ::: "memory")
#define CP_WAIT(n)  asm volatile("cp.async.wait_group %0;" :: "n"(n) : "memory")

__device__ __forceinline__ u32 h2_u32(float a, float b) {
    __half2 h = __floats2half2_rn(a, b);
    return *reinterpret_cast<u32*>(&h);
}

// ===================== device scratch =====================
__device__ __half d_imTh[8 * 256 * 2048];         // [b][hw][cin] fp16
__device__ __half d_pwH[1024 * 2048];             // proj_w fp16
__device__ __half d_xh[8 * 256 * 1024];           // projected feats fp16
__device__ float d_tb[256];
__device__ __half d_Rh[512ull * 49 * 1024];       // roi feats fp16
__device__ __half d_Wc[256ull * 9216];            // conv w fp16 [o][t*1024+ci]
__device__ float d_cvp[2ull * 25088 * 256];       // conv split-K partials f32
__device__ __half d_r1h[512ull * 12544];          // conv out fp16, K order p*256+o
__device__ __half d_fcWh[1024ull * 12544];        // fc w fp16, K reordered
__device__ float d_fcp[14ull * 512 * 1024];       // FC split-K partials
__device__ __half d_featsH[512 * 1280];           // LN'd features fp16
__device__ __half d_g1H[2560 * 1280];             // g1 rearranged: [U rows | V rows][1280]
__device__ float d_g1b2[2560];                    // [g1_b | zeros]
__device__ __half d_UVh[512 * 2560];              // [row][U'(+bias) 1280 | V 1280] fp16
__device__ __half d_h2h[32768ull * 1280];
__device__ __half d_w2h[1280ull * 1280];
__device__ __half d_w3h[1280ull * 1280];
__device__ float d_gp[256 * 1280];

// ===================== prep kernels =====================
__global__ void transpose_bchw_h(const float* __restrict__ in, __half* __restrict__ out) {
    __shared__ float tile[32][33];
    int b = blockIdx.z, p0 = blockIdx.x * 32, c0 = blockIdx.y * 32;
    int tx = threadIdx.x, ty = threadIdx.y;
    const float* ip = in + (long long)b * 2048 * 256;
    #pragma unroll
    for (int i = 0; i < 32; i += 8) tile[ty + i][tx] = ip[(c0 + ty + i) * 256 + p0 + tx];
    __syncthreads();
    __half* op = out + (long long)b * 256 * 2048;
    #pragma unroll
    for (int i = 0; i < 32; i += 8)
        op[(p0 + ty + i) * 2048 + c0 + tx] = __float2half_rn(tile[tx][ty + i]);
}

__global__ void conv_f2h(const float* __restrict__ in, __half* __restrict__ out, int n) {
    int i = blockIdx.x * 256 + threadIdx.x;
    if (i < n) out[i] = __float2half_rn(in[i]);
}

// merged small preps: g2_w->w2h, g3_w->w3h, g1 rearrange, g1b pad, tb fold
__global__ void prep_misc(const float* __restrict__ g2w, const float* __restrict__ g3w,
                          const float* __restrict__ g1w, const float* __restrict__ g1b,
                          const float* __restrict__ cb, const float* __restrict__ bg,
                          const float* __restrict__ bb, const float* __restrict__ bm,
                          const float* __restrict__ bv,
                          __half* __restrict__ w2h, __half* __restrict__ w3h,
                          __half* __restrict__ g1H, float* __restrict__ g1b2,
                          float* __restrict__ tb)
{
    int blk = blockIdx.x;
    int tid = threadIdx.x;
    if (blk < 6400) {
        int i = blk * 256 + tid;
        w2h[i] = __float2half_rn(g2w[i]);
    } else if (blk < 12800) {
        int i = (blk - 6400) * 256 + tid;
        w3h[i] = __float2half_rn(g3w[i]);
    } else if (blk < 25600) {
        int i = (blk - 12800) * 256 + tid;   // < 2560*1280
        int n = i / 1280, k = i - n * 1280;
        int srcRow = (n >= 1280) ? (n - 1280) : n;
        int srcCol = ((n >= 1280) ? 1280 : 0) + k;
        g1H[i] = __float2half_rn(g1w[(size_t)srcRow * 2560 + srcCol]);
    } else if (blk < 25610) {
        int i = (blk - 25600) * 256 + tid;   // < 2560
        g1b2[i] = (i < 1280) ? g1b[i] : 0.f;
    } else {
        int o = tid;
        float s = bg[o] * rsqrtf(bv[o] + CEPS);
        tb[o] = (cb[o] - bm[o]) * s + bb[o];
    }
}

__global__ void prep_convw_fp16(const float* __restrict__ cw, const float* __restrict__ g,
                                const float* __restrict__ vv, __half* __restrict__ Wc) {
    __shared__ float sf[9216];
    int o = blockIdx.x;
    for (int j = threadIdx.x; j < 9216; j += 256) sf[j] = cw[o * 9216 + j];   // [ci][t]
    __syncthreads();
    float s = g[o] * rsqrtf(vv[o] + CEPS);
    for (int r = threadIdx.x; r < 9216; r += 256) {
        int t = r >> 10, ci = r & 1023;
        Wc[(size_t)o * 9216 + r] = __float2half_rn(sf[ci * 9 + t] * s);
    }
}

__global__ void prep_fcw(const float* __restrict__ fw, __half* __restrict__ o) {
    extern __shared__ float sf[];   // 12544 floats
    int n = blockIdx.x;
    for (int j = threadIdx.x; j < 12544; j += 256) sf[j] = fw[n * 12544 + j];
    __syncthreads();
    for (int j = threadIdx.x; j < 12544; j += 256) {
        int p = j >> 8, oo = j & 255;
        o[(size_t)n * 12544 + j] = __float2half_rn(sf[oo * 49 + p]);
    }
}

// conv split-K reduce: r1h = relu(P0 + P1 + tb)
__global__ void conv_reduce(const float* __restrict__ P, const float* __restrict__ tb,
                            __half* __restrict__ r1h) {
    int i = blockIdx.x * 256 + threadIdx.x;
    int e = i * 2;
    float2 a = *(const float2*)(P + e);
    float2 b = *(const float2*)(P + 25088ull * 256 + e);
    int col = e & 255;
    float v0 = fmaxf(a.x + b.x + tb[col], 0.f);
    float v1 = fmaxf(a.y + b.y + tb[col + 1], 0.f);
    *(u32*)(r1h + e) = h2_u32(v0, v1);
}

// ===================== HMMA GEMM: pure fp16, fp32 accum ====================
// 128x128 tile, 8 warps (2M x 4N, 64x32 each), K chunks of 64,
// 2-stage cp.async double buffer.
// MODE 0: g2 (A tile built on the fly: relu(U'+V) from UVh)
// MODE 1: g3   MODE 3: FC   MODE 4: proj   MODE 5: UV (+bias, fp16, ldc 2560)
// MODE 6: conv split-K (z over 2 halves of 144 chunks), raw f32 partials
template<int MODE>
__global__ void __launch_bounds__(256, 2) hgemm(
    const __half* __restrict__ A, const __half* __restrict__ B,
    const float* __restrict__ bias,
    __half* __restrict__ outH, float* __restrict__ outF,
    int nkin, int lda, int ldb)
{
    extern __shared__ char dsm[];
    const u32 raw = smem_u32(dsm);
    const u32 base = (raw + 1023u) & ~1023u;
    char* smem_g = dsm + (base - raw);

    const int tid = threadIdx.x;
    const int lane = tid & 31;
    const int w = tid >> 5;
    const int wM = w >> 2, wN = w & 3;
    const int nB = blockIdx.x * 128, mB = blockIdx.y * 128;
    const int kinBase = (MODE == 3 || MODE == 6) ? blockIdx.z * nkin : 0;

    const int lrow = tid >> 3, lc16 = tid & 7;

    int cn4[4], cy4[4], cx4[4];
    if (MODE == 6) {
        #pragma unroll
        for (int p = 0; p < 4; p++) {
            int r = mB + p * 32 + lrow;
            int n = r / 49, pp = r - n * 49;
            cn4[p] = n; cy4[p] = pp / 7; cx4[p] = pp - (pp / 7) * 7;
        }
    }
    int ru[4], rv[4];
    if (MODE == 0) {
        #pragma unroll
        for (int p = 0; p < 4; p++) {
            int row = mB + p * 32 + lrow;
            int img = row >> 12, a = (row >> 6) & 63, b = row & 63;
            ru[p] = img * 64 + b;
            rv[p] = img * 64 + a;
        }
    }

    u32 soff[4];
    #pragma unroll
    for (int p = 0; p < 4; p++) {
        u32 off = (u32)(((p * 32 + lrow) << 7) | (lc16 << 4));
        soff[p] = SWZ128(off);
    }

    auto gload = [&](int c, int s) {
        int kin = kinBase + c;
        u32 sg = base + (u32)s * 32768u;
        char* sgp = smem_g + (size_t)s * 32768u;
        int kOff = (kin << 6) + (lc16 << 3);
        if (MODE == 6) {
            int t = kin >> 4, ci0 = (kin & 15) << 6;
            int dy = t / 3 - 1, dx = t - (t / 3) * 3 - 1;
            #pragma unroll
            for (int p = 0; p < 4; p++) {
                int iy = cy4[p] + dy, ix = cx4[p] + dx;
                bool ok = (iy >= 0) && (iy < 7) && (ix >= 0) && (ix < 7);
                const __half* src = ok ?
                    (A + (((size_t)(cn4[p] * 49 + iy * 7 + ix)) << 10) + ci0 + (lc16 << 3)) : A;
                cpa16z(sg + soff[p], src, ok);
            }
        } else if (MODE == 0) {
            const __half2 z2 = __float2half2_rn(0.f);
            #pragma unroll
            for (int p = 0; p < 4; p++) {
                uint4 uv = *(const uint4*)(A + (size_t)ru[p] * 2560 + kOff);
                uint4 vv = *(const uint4*)(A + (size_t)rv[p] * 2560 + 1280 + kOff);
                const __half2* u2 = (const __half2*)&uv;
                const __half2* v2 = (const __half2*)&vv;
                uint4 r;
                __half2* r2 = (__half2*)&r;
                #pragma unroll
                for (int q = 0; q < 4; q++) r2[q] = __hmax2(__hadd2(u2[q], v2[q]), z2);
                *(uint4*)(sgp + soff[p]) = r;
            }
        } else {
            #pragma unroll
            for (int p = 0; p < 4; p++)
                cpa16(sg + soff[p], A + (size_t)(mB + p * 32 + lrow) * lda + kOff);
        }
        #pragma unroll
        for (int p = 0; p < 4; p++)
            cpa16(sg + 16384u + soff[p], B + (size_t)(nB + p * 32 + lrow) * ldb + kOff);
    };

    float acc[4][4][4];
    #pragma unroll
    for (int mi = 0; mi < 4; mi++)
        #pragma unroll
        for (int ni = 0; ni < 4; ni++)
            #pragma unroll
            for (int r = 0; r < 4; r++) acc[mi][ni][r] = 0.f;

    const u32 aRow = (u32)(wM * 64 + (lane & 15));
    const u32 aSegX = (lane & 16) ? 16u : 0u;
    const u32 bRow = (u32)(wN * 32 + (lane & 7) + ((lane & 16) ? 8 : 0));
    const u32 bSegX = (lane & 8) ? 16u : 0u;

    gload(0, 0); CP_COMMIT();
    if (nkin > 1) { gload(1, 1); CP_COMMIT(); }

    for (int c = 0; c < nkin; c++) {
        int s = c & 1;
        if (c + 1 < nkin) { CP_WAIT(1); } else { CP_WAIT(0); }
        __syncthreads();
        u32 aBase = base + (u32)s * 32768u;
        u32 bB = aBase + 16384u;
        #pragma unroll
        for (int ks = 0; ks < 4; ks++) {
            u32 kb = (u32)(ks * 32);
            u32 afr[4][4];
            #pragma unroll
            for (int mi = 0; mi < 4; mi++)
                ldsm4(afr[mi][0], afr[mi][1], afr[mi][2], afr[mi][3],
                      aBase + SWZ128(((aRow + mi * 16) << 7) + kb + aSegX));
            u32 bfr[4][2];
            #pragma unroll
            for (int q = 0; q < 2; q++) {
                u32 r0, r1, r2, r3;
                ldsm4(r0, r1, r2, r3, bB + SWZ128(((bRow + q * 16) << 7) + kb + bSegX));
                bfr[2 * q][0] = r0; bfr[2 * q][1] = r1;
                bfr[2 * q + 1][0] = r2; bfr[2 * q + 1][1] = r3;
            }
            #pragma unroll
            for (int mi = 0; mi < 4; mi++)
                #pragma unroll
                for (int ni = 0; ni < 4; ni++)
                    mma16816(acc[mi][ni], afr[mi], bfr[ni]);
        }
        __syncthreads();
        if (c + 2 < nkin) { gload(c + 2, s); CP_COMMIT(); }
    }

    // ---------------- epilogue ----------------
    const int gRow0 = mB + wM * 64 + (lane >> 2);
    const int gCol0 = nB + wN * 32 + (lane & 3) * 2;

    if (MODE == 0) {
        #pragma unroll
        for (int mi = 0; mi < 4; mi++)
            #pragma unroll
            for (int rg = 0; rg < 2; rg++) {
                int row = gRow0 + mi * 16 + rg * 8;
                #pragma unroll
                for (int ni = 0; ni < 4; ni++) {
                    int col = gCol0 + ni * 8;
                    float v0 = fmaxf(acc[mi][ni][rg * 2] + bias[col], 0.f);
                    float v1 = fmaxf(acc[mi][ni][rg * 2 + 1] + bias[col + 1], 0.f);
                    *(u32*)(outH + (size_t)row * 1280 + col) = h2_u32(v0, v1);
                }
            }
    } else if (MODE == 1) {
        float s0[4], s1[4];
        #pragma unroll
        for (int ni = 0; ni < 4; ni++) {
            int col = gCol0 + ni * 8;
            float b0 = bias[col], b1 = bias[col + 1];
            float t0 = 0.f, t1 = 0.f;
            #pragma unroll
            for (int mi = 0; mi < 4; mi++) {
                t0 += fmaxf(acc[mi][ni][0] + b0, 0.f) + fmaxf(acc[mi][ni][2] + b0, 0.f);
                t1 += fmaxf(acc[mi][ni][1] + b1, 0.f) + fmaxf(acc[mi][ni][3] + b1, 0.f);
            }
            #pragma unroll
            for (int m = 4; m < 32; m <<= 1) {
                t0 += __shfl_xor_sync(0xffffffffu, t0, m);
                t1 += __shfl_xor_sync(0xffffffffu, t1, m);
            }
            s0[ni] = t0; s1[ni] = t1;
        }
        float* CS = (float*)dsm;
        __syncthreads();
        if (lane < 4) {
            #pragma unroll
            for (int ni = 0; ni < 4; ni++) {
                int colL = wN * 32 + ni * 8 + lane * 2;
                CS[wM * 128 + colL] = s0[ni];
                CS[wM * 128 + colL + 1] = s1[ni];
            }
        }
        __syncthreads();
        if (tid < 128)
            outF[(size_t)blockIdx.y * 1280 + nB + tid] = CS[tid] + CS[128 + tid];
    } else if (MODE == 3) {
        float* Fout = outF + (size_t)blockIdx.z * 512 * 1024;
        #pragma unroll
        for (int mi = 0; mi < 4; mi++)
            #pragma unroll
            for (int rg = 0; rg < 2; rg++) {
                int row = gRow0 + mi * 16 + rg * 8;
                #pragma unroll
                for (int ni = 0; ni < 4; ni++) {
                    int col = gCol0 + ni * 8;
                    *(float2*)(Fout + (size_t)row * 1024 + col) =
                        make_float2(acc[mi][ni][rg * 2], acc[mi][ni][rg * 2 + 1]);
                }
            }
    } else if (MODE == 4) {
        #pragma unroll
        for (int mi = 0; mi < 4; mi++)
            #pragma unroll
            for (int rg = 0; rg < 2; rg++) {
                int row = gRow0 + mi * 16 + rg * 8;
                #pragma unroll
                for (int ni = 0; ni < 4; ni++) {
                    int col = gCol0 + ni * 8;
                    float v0 = acc[mi][ni][rg * 2] + bias[col];
                    float v1 = acc[mi][ni][rg * 2 + 1] + bias[col + 1];
                    *(u32*)(outH + (size_t)row * 1024 + col) = h2_u32(v0, v1);
                }
            }
    } else if (MODE == 5) {
        #pragma unroll
        for (int mi = 0; mi < 4; mi++)
            #pragma unroll
            for (int rg = 0; rg < 2; rg++) {
                int row = gRow0 + mi * 16 + rg * 8;
                #pragma unroll
                for (int ni = 0; ni < 4; ni++) {
                    int col = gCol0 + ni * 8;
                    float v0 = acc[mi][ni][rg * 2] + bias[col];
                    float v1 = acc[mi][ni][rg * 2 + 1] + bias[col + 1];
                    *(u32*)(outH + (size_t)row * 2560 + col) = h2_u32(v0, v1);
                }
            }
    } else {   // MODE 6: conv partials raw f32, ldc 256
        float* Fout = outF + (size_t)blockIdx.z * 25088 * 256;
        #pragma unroll
        for (int mi = 0; mi < 4; mi++)
            #pragma unroll
            for (int rg = 0; rg < 2; rg++) {
                int row = gRow0 + mi * 16 + rg * 8;
                #pragma unroll
                for (int ni = 0; ni < 4; ni++) {
                    int col = gCol0 + ni * 8;
                    *(float2*)(Fout + (size_t)row * 256 + col) =
                        make_float2(acc[mi][ni][rg * 2], acc[mi][ni][rg * 2 + 1]);
                }
            }
    }
}

// ===================== ROIAlign (fp16 in/out) =====================
__global__ void roialign_fp16(const __half* __restrict__ x, const float* __restrict__ boxes,
                              __half* __restrict__ oh)
{
    int blk = blockIdx.x;     // 0..25087
    int n = blk / 49;
    int bin = blk - n * 49;
    int by = bin / 7, bx = bin - by * 7;
    int b = n >> 6;
    const float* roi = boxes + n * 4;
    float x1 = roi[0] * (1.f / 32.f) - 0.5f;
    float y1 = roi[1] * (1.f / 32.f) - 0.5f;
    float bw = (roi[2] - roi[0]) * (1.f / 32.f) * (1.f / 7.f);
    float bh = (roi[3] - roi[1]) * (1.f / 32.f) * (1.f / 7.f);
    int pidx[16];
    float pw[16];
    int cnt = 0;
    #pragma unroll
    for (int sy = 0; sy < 2; sy++) {
        float ys = y1 + bh * ((float)by + (sy + 0.5f) * 0.5f);
        bool vy = (ys >= -1.f) && (ys <= 16.f);
        float v = fmaxf(ys, 0.f);
        int lo = (int)floorf(v);
        int yl, yh; float wy;
        if (lo >= 15) { yl = 15; yh = 15; wy = 0.f; }
        else { yl = lo; yh = lo + 1; wy = v - (float)lo; }
        #pragma unroll
        for (int sx = 0; sx < 2; sx++) {
            float xs = x1 + bw * ((float)bx + (sx + 0.5f) * 0.5f);
            bool vx = (xs >= -1.f) && (xs <= 16.f);
            float u = fmaxf(xs, 0.f);
            int lo2 = (int)floorf(u);
            int xl, xh; float wx;
            if (lo2 >= 15) { xl = 15; xh = 15; wx = 0.f; }
            else { xl = lo2; xh = lo2 + 1; wx = u - (float)lo2; }
            float m = (vy && vx) ? 0.25f : 0.f;
            pidx[cnt] = yl * 16 + xl; pw[cnt] = (1.f - wy) * (1.f - wx) * m; cnt++;
            pidx[cnt] = yl * 16 + xh; pw[cnt] = (1.f - wy) * wx * m;         cnt++;
            pidx[cnt] = yh * 16 + xl; pw[cnt] = wy * (1.f - wx) * m;         cnt++;
            pidx[cnt] = yh * 16 + xh; pw[cnt] = wy * wx * m;                 cnt++;
        }
    }
    const __half* xb = x + ((long long)b << 18);
    int c = threadIdx.x * 4;
    float acc0 = 0.f, acc1 = 0.f, acc2 = 0.f, acc3 = 0.f;
    #pragma unroll
    for (int t = 0; t < 16; t++) {
        uint2 hv = *(const uint2*)(xb + (pidx[t] << 10) + c);
        float2 f0 = __half22float2(*reinterpret_cast<__half2*>(&hv.x));
        float2 f1 = __half22float2(*reinterpret_cast<__half2*>(&hv.y));
        acc0 += pw[t] * f0.x; acc1 += pw[t] * f0.y;
        acc2 += pw[t] * f1.x; acc3 += pw[t] * f1.y;
    }
    size_t o = ((size_t)blk << 10) + c;
    *(uint2*)(oh + o) = make_uint2(h2_u32(acc0, acc1), h2_u32(acc2, acc3));
}

// ===================== FC reduce + LN1 (fp16 out) =====================
__global__ void fc_reduce_ln(const float* __restrict__ part, const float* __restrict__ fcb,
                             const float* __restrict__ g, const float* __restrict__ b,
                             __half* __restrict__ featsH)
{
    __shared__ float sv[1024];
    __shared__ float red[256];
    int n = blockIdx.x, tid = threadIdx.x;
    float s = 0.f;
    #pragma unroll
    for (int i = 0; i < 4; i++) {
        int col = i * 256 + tid;
        float v = fcb[col];
        #pragma unroll
        for (int z = 0; z < 14; z++) v += part[(long long)((z << 9) + n) * 1024 + col];
        v = fmaxf(v, 0.f);
        sv[col] = v;
        s += v;
    }
    red[tid] = s; __syncthreads();
    for (int st = 128; st > 0; st >>= 1) { if (tid < st) red[tid] += red[tid + st]; __syncthreads(); }
    float mu = red[0] * (1.f / 1024.f);
    __syncthreads();
    float q = 0.f;
    #pragma unroll
    for (int i = 0; i < 4; i++) { float d = sv[i * 256 + tid] - mu; q += d * d; }
    red[tid] = q; __syncthreads();
    for (int st = 128; st > 0; st >>= 1) { if (tid < st) red[tid] += red[tid + st]; __syncthreads(); }
    float rstd = rsqrtf(red[0] * (1.f / 1024.f) + CEPS);
    #pragma unroll
    for (int i = 0; i < 4; i++) {
        int col = i * 256 + tid;
        featsH[(long long)n * 1280 + col] =
            __float2half_rn((sv[col] - mu) * rstd * g[col] + b[col]);
    }
}

// ===================== box branch (fp16 out) =====================
__global__ void box_ln(const float* __restrict__ nbx, const float* __restrict__ bw,
                       const float* __restrict__ bb, const float* __restrict__ g,
                       const float* __restrict__ be, __half* __restrict__ featsH)
{
    __shared__ float red[256];
    int n = blockIdx.x, tid = threadIdx.x;
    float a0 = nbx[n * 4 + 0] * 2.f - 1.f;
    float a1 = nbx[n * 4 + 1] * 2.f - 1.f;
    float a2 = nbx[n * 4 + 2] * 2.f - 1.f;
    float a3 = nbx[n * 4 + 3] * 2.f - 1.f;
    const float* w = bw + tid * 4;
    float v = w[0] * a0 + w[1] * a1 + w[2] * a2 + w[3] * a3 + bb[tid];
    red[tid] = v; __syncthreads();
    for (int st = 128; st > 0; st >>= 1) { if (tid < st) red[tid] += red[tid + st]; __syncthreads(); }
    float mu = red[0] * (1.f / 256.f);
    __syncthreads();
    float d = v - mu;
    red[tid] = d * d; __syncthreads();
    for (int st = 128; st > 0; st >>= 1) { if (tid < st) red[tid] += red[tid + st]; __syncthreads(); }
    float rstd = rsqrtf(red[0] * (1.f / 256.f) + CEPS);
    featsH[(long long)n * 1280 + 1024 + tid] =
        __float2half_rn((v - mu) * rstd * g[tid] + be[tid]);
}

// ===================== final reduce =====================
__global__ void final_reduce(const float* __restrict__ gp, float* __restrict__ out)
{
    int i = blockIdx.x * 256 + threadIdx.x;   // < 10240
    int img = i / 1280, j = i - img * 1280;
    float s = 0.f;
    #pragma unroll
    for (int mb = 0; mb < 32; mb++)
        s += gp[(long long)(img * 32 + mb) * 1280 + j];
    out[i] = s;
}

// ===================== launch =====================
extern "C" void kernel_launch(void* const* d_in, const int* in_sizes, int n_in,
                              void* d_out, int out_size)
{
    const float* im_feat = (const float*)d_in[0];
    const float* boxes   = (const float*)d_in[1];
    const float* nboxes  = (const float*)d_in[2];
    const float* proj_w  = (const float*)d_in[3];
    const float* proj_b  = (const float*)d_in[4];
    const float* conv_w  = (const float*)d_in[5];
    const float* conv_b  = (const float*)d_in[6];
    const float* bn_g = (const float*)d_in[7];
    const float* bn_b = (const float*)d_in[8];
    const float* bn_m = (const float*)d_in[9];
    const float* bn_v = (const float*)d_in[10];
    const float* fc_w = (const float*)d_in[11];
    const float* fc_b = (const float*)d_in[12];
    const float* ln1_g = (const float*)d_in[13];
    const float* ln1_b = (const float*)d_in[14];
    const float* box_w = (const float*)d_in[15];
    const float* box_b = (const float*)d_in[16];
    const float* ln2_g = (const float*)d_in[17];
    const float* ln2_b = (const float*)d_in[18];
    const float* g1_w = (const float*)d_in[19];
    const float* g1_b = (const float*)d_in[20];
    const float* g2_w = (const float*)d_in[21];
    const float* g2_b = (const float*)d_in[22];
    const float* g3_w = (const float*)d_in[23];
    const float* g3_b = (const float*)d_in[24];
    float* out = (float*)d_out;

    float *p_tb, *p_cvp, *p_fcp, *p_g1b2, *p_gp;
    __half *p_imTh, *p_pwH, *p_xh, *p_Rh, *p_Wc, *p_r1h, *p_fcWh, *p_featsH, *p_g1H,
           *p_UVh, *p_h2h, *p_w2h, *p_w3h;
    cudaGetSymbolAddress((void**)&p_imTh, d_imTh);
    cudaGetSymbolAddress((void**)&p_pwH, d_pwH);
    cudaGetSymbolAddress((void**)&p_xh, d_xh);
    cudaGetSymbolAddress((void**)&p_tb, d_tb);
    cudaGetSymbolAddress((void**)&p_cvp, d_cvp);
    cudaGetSymbolAddress((void**)&p_fcp, d_fcp);
    cudaGetSymbolAddress((void**)&p_featsH, d_featsH);
    cudaGetSymbolAddress((void**)&p_g1H, d_g1H);
    cudaGetSymbolAddress((void**)&p_g1b2, d_g1b2);
    cudaGetSymbolAddress((void**)&p_UVh, d_UVh);
    cudaGetSymbolAddress((void**)&p_gp, d_gp);
    cudaGetSymbolAddress((void**)&p_Rh, d_Rh);
    cudaGetSymbolAddress((void**)&p_Wc, d_Wc);
    cudaGetSymbolAddress((void**)&p_r1h, d_r1h);
    cudaGetSymbolAddress((void**)&p_fcWh, d_fcWh);
    cudaGetSymbolAddress((void**)&p_h2h, d_h2h);
    cudaGetSymbolAddress((void**)&p_w2h, d_w2h);
    cudaGetSymbolAddress((void**)&p_w3h, d_w3h);

    const int SMEMSZ = 2 * 32768 + 1024;   // 66560
    cudaFuncSetAttribute(hgemm<0>, cudaFuncAttributeMaxDynamicSharedMemorySize, SMEMSZ);
    cudaFuncSetAttribute(hgemm<1>, cudaFuncAttributeMaxDynamicSharedMemorySize, SMEMSZ);
    cudaFuncSetAttribute(hgemm<3>, cudaFuncAttributeMaxDynamicSharedMemorySize, SMEMSZ);
    cudaFuncSetAttribute(hgemm<4>, cudaFuncAttributeMaxDynamicSharedMemorySize, SMEMSZ);
    cudaFuncSetAttribute(hgemm<5>, cudaFuncAttributeMaxDynamicSharedMemorySize, SMEMSZ);
    cudaFuncSetAttribute(hgemm<6>, cudaFuncAttributeMaxDynamicSharedMemorySize, SMEMSZ);
    cudaFuncSetAttribute(prep_fcw, cudaFuncAttributeMaxDynamicSharedMemorySize, 50176);

    // launch #4 = roialign (ncu samples position 4)
    transpose_bchw_h<<<dim3(8, 64, 8), dim3(32, 8)>>>(im_feat, p_imTh);          // 1
    conv_f2h<<<8192, 256>>>(proj_w, p_pwH, 1024 * 2048);                          // 2
    hgemm<4><<<dim3(8, 16), 256, SMEMSZ>>>(p_imTh, p_pwH, proj_b, p_xh, nullptr,  // 3
                                           32, 2048, 2048);
    roialign_fp16<<<25088, 256>>>(p_xh, boxes, p_Rh);                             // 4  <- profiled
    prep_convw_fp16<<<256, 256>>>(conv_w, bn_g, bn_v, p_Wc);                      // 5
    prep_misc<<<25611, 256>>>(g2_w, g3_w, g1_w, g1_b, conv_b, bn_g, bn_b, bn_m,   // 6
                              bn_v, p_w2h, p_w3h, p_g1H, p_g1b2, p_tb);
    hgemm<6><<<dim3(2, 196, 2), 256, SMEMSZ>>>(p_Rh, p_Wc, nullptr, nullptr,      // 7
                                               p_cvp, 72, 0, 9216);
    conv_reduce<<<12544, 256>>>(p_cvp, p_tb, p_r1h);                              // 8
    prep_fcw<<<1024, 256, 50176>>>(fc_w, p_fcWh);                                 // 9
    hgemm<3><<<dim3(8, 4, 14), 256, SMEMSZ>>>(p_r1h, p_fcWh, nullptr, nullptr,    // 10
                                              p_fcp, 14, 12544, 12544);
    fc_reduce_ln<<<512, 256>>>(p_fcp, fc_b, ln1_g, ln1_b, p_featsH);              // 11
    box_ln<<<512, 256>>>(nboxes, box_w, box_b, ln2_g, ln2_b, p_featsH);           // 12
    hgemm<5><<<dim3(20, 4), 256, SMEMSZ>>>(p_featsH, p_g1H, p_g1b2, p_UVh,        // 13
                                           nullptr, 20, 1280, 1280);
    hgemm<0><<<dim3(10, 256), 256, SMEMSZ>>>(p_UVh, p_w2h, g2_b, p_h2h, nullptr,  // 14
                                             20, 2560, 1280);
    hgemm<1><<<dim3(10, 256), 256, SMEMSZ>>>(p_h2h, p_w3h, g3_b, nullptr, p_gp,   // 15
                                             20, 1280, 1280);
    final_reduce<<<40, 256>>>(p_gp, out);                                         // 16
}

// round 16
// speedup vs baseline: 1.0377x; 1.0336x over previous
#include <cuda_runtime.h>
#include <cuda_fp16.h>
#include <cstdint>

typedef unsigned long long u64;
typedef unsigned int u32;
#define CEPS 1e-5f

// ===================== helpers =====================
__device__ __forceinline__ u32 smem_u32(const void* p) {
    u32 a;
    asm("{ .reg .u64 t; cvta.to.shared.u64 t, %1; cvt.u32.u64 %0, t; }" : "=r"(a) : "l"(p));
    return a;
}
#define SWZ128(o) ((o) ^ (((o) >> 3) & 0x70))

__device__ __forceinline__ void ldsm4(u32& r0, u32& r1, u32& r2, u32& r3, u32 addr) {
    asm volatile("ldmatrix.sync.aligned.m8n8.x4.shared.b16 {%0,%1,%2,%3}, [%4];"
        : "=r"(r0), "=r"(r1), "=r"(r2), "=r"(r3) : "r"(addr));
}
__device__ __forceinline__ void mma16816(float* c, const u32* a, const u32* b) {
    asm volatile("mma.sync.aligned.m16n8k16.row.col.f32.f16.f16.f32 "
        "{%0,%1,%2,%3}, {%4,%5,%6,%7}, {%8,%9}, {%0,%1,%2,%3};"
        : "+f"(c[0]), "+f"(c[1]), "+f"(c[2]), "+f"(c[3])
        : "r"(a[0]), "r"(a[1]), "r"(a[2]), "r"(a[3]), "r"(b[0]), "r"(b[1]));
}
__device__ __forceinline__ void cpa16(u32 dst, const void* src) {
    asm volatile("cp.async.cg.shared.global [%0], [%1], 16;" :: "r"(dst), "l"(src));
}
__device__ __forceinline__ void cpa16z(u32 dst, const void* src, bool ok) {
    u32 sz = ok ? 16u : 0u;
    asm volatile("cp.async.cg.shared.global [%0], [%1], 16, %2;" :: "r"(dst), "l"(src), "r"(sz));
}
#define CP_COMMIT() asm volatile("cp.async.commit_group;" ::: "memory")
#define CP_WAIT(n)  asm volatile("cp.async.wait_group %0;" :: "n"(n) : "memory")

__device__ __forceinline__ u32 h2_u32(float a, float b) {
    __half2 h = __floats2half2_rn(a, b);
    return *reinterpret_cast<u32*>(&h);
}

// ===================== device scratch =====================
__device__ __half d_imTh[8 * 256 * 2048];         // [b][hw][cin] fp16
__device__ __half d_pwH[1024 * 2048];             // proj_w fp16
__device__ __half d_xh[8 * 256 * 1024];           // projected feats fp16
__device__ float d_tb[256];
__device__ u32 d_geoW[25088 * 16];                // per-(roi,bin) half2-splat weights
__device__ u32 d_geoI[25088 * 4];                 // per-(roi,bin) 16 packed u8 indices
__device__ __half d_Rh[512ull * 49 * 1024];       // roi feats fp16
__device__ __half d_Wc[256ull * 9216];            // conv w fp16 [o][t*1024+ci]
__device__ float d_cvp[2ull * 25088 * 256];       // conv split-K partials f32
__device__ __half d_r1h[512ull * 12544];          // conv out fp16, K order p*256+o
__device__ __half d_fcWh[1024ull * 12544];        // fc w fp16, K reordered
__device__ float d_fcp[14ull * 512 * 1024];       // FC split-K partials
__device__ __half d_featsH[512 * 1280];           // LN'd features fp16
__device__ __half d_g1H[2560 * 1280];             // g1 rearranged: [U rows | V rows][1280]
__device__ float d_g1b2[2560];                    // [g1_b | zeros]
__device__ __half d_UVh[512 * 2560];              // [row][U'(+bias) 1280 | V 1280] fp16
__device__ __half d_h2h[32768ull * 1280];
__device__ __half d_w2h[1280ull * 1280];
__device__ __half d_w3h[1280ull * 1280];
__device__ float d_gp[256 * 1280];

// ===================== prep kernels =====================
__global__ void transpose_bchw_h(const float* __restrict__ in, __half* __restrict__ out) {
    __shared__ float tile[32][33];
    int b = blockIdx.z, p0 = blockIdx.x * 32, c0 = blockIdx.y * 32;
    int tx = threadIdx.x, ty = threadIdx.y;
    const float* ip = in + (long long)b * 2048 * 256;
    #pragma unroll
    for (int i = 0; i < 32; i += 8) tile[ty + i][tx] = ip[(c0 + ty + i) * 256 + p0 + tx];
    __syncthreads();
    __half* op = out + (long long)b * 256 * 2048;
    #pragma unroll
    for (int i = 0; i < 32; i += 8)
        op[(p0 + ty + i) * 2048 + c0 + tx] = __float2half_rn(tile[tx][ty + i]);
}

__global__ void conv_f2h(const float* __restrict__ in, __half* __restrict__ out, int n) {
    int i = blockIdx.x * 256 + threadIdx.x;
    if (i < n) out[i] = __float2half_rn(in[i]);
}

// ROIAlign geometry: one thread per (roi, bin)
__global__ void roi_geom(const float* __restrict__ boxes,
                         u32* __restrict__ geoW, u32* __restrict__ geoI)
{
    int blk = blockIdx.x * 256 + threadIdx.x;
    if (blk >= 25088) return;
    int n = blk / 49;
    int bin = blk - n * 49;
    int by = bin / 7, bx = bin - by * 7;
    const float* roi = boxes + n * 4;
    float x1 = roi[0] * (1.f / 32.f) - 0.5f;
    float y1 = roi[1] * (1.f / 32.f) - 0.5f;
    float bw = (roi[2] - roi[0]) * (1.f / 32.f) * (1.f / 7.f);
    float bh = (roi[3] - roi[1]) * (1.f / 32.f) * (1.f / 7.f);
    int pidx[16];
    float pw[16];
    int cnt = 0;
    #pragma unroll
    for (int sy = 0; sy < 2; sy++) {
        float ys = y1 + bh * ((float)by + (sy + 0.5f) * 0.5f);
        bool vy = (ys >= -1.f) && (ys <= 16.f);
        float v = fmaxf(ys, 0.f);
        int lo = (int)floorf(v);
        int yl, yh; float wy;
        if (lo >= 15) { yl = 15; yh = 15; wy = 0.f; }
        else { yl = lo; yh = lo + 1; wy = v - (float)lo; }
        #pragma unroll
        for (int sx = 0; sx < 2; sx++) {
            float xs = x1 + bw * ((float)bx + (sx + 0.5f) * 0.5f);
            bool vx = (xs >= -1.f) && (xs <= 16.f);
            float u = fmaxf(xs, 0.f);
            int lo2 = (int)floorf(u);
            int xl, xh; float wx;
            if (lo2 >= 15) { xl = 15; xh = 15; wx = 0.f; }
            else { xl = lo2; xh = lo2 + 1; wx = u - (float)lo2; }
            float m = (vy && vx) ? 0.25f : 0.f;
            pidx[cnt] = yl * 16 + xl; pw[cnt] = (1.f - wy) * (1.f - wx) * m; cnt++;
            pidx[cnt] = yl * 16 + xh; pw[cnt] = (1.f - wy) * wx * m;         cnt++;
            pidx[cnt] = yh * 16 + xl; pw[cnt] = wy * (1.f - wx) * m;         cnt++;
            pidx[cnt] = yh * 16 + xh; pw[cnt] = wy * wx * m;                 cnt++;
        }
    }
    #pragma unroll
    for (int t = 0; t < 16; t++) {
        __half h = __float2half_rn(pw[t]);
        u32 hb = (u32)__half_as_ushort(h);
        geoW[blk * 16 + t] = hb | (hb << 16);
    }
    #pragma unroll
    for (int q = 0; q < 4; q++) {
        geoI[blk * 4 + q] = (u32)pidx[4 * q] | ((u32)pidx[4 * q + 1] << 8) |
                            ((u32)pidx[4 * q + 2] << 16) | ((u32)pidx[4 * q + 3] << 24);
    }
}

// ROIAlign gather: 128 threads x 8 channels, half2 accumulation
__global__ void __launch_bounds__(128) roialign_gather(
    const __half* __restrict__ x, const u32* __restrict__ geoW,
    const u32* __restrict__ geoI, __half* __restrict__ oh)
{
    __shared__ u32 sw[16];
    __shared__ u32 sidx[16];
    int blk = blockIdx.x;
    int tid = threadIdx.x;
    if (tid < 16) {
        sw[tid] = geoW[blk * 16 + tid];
        u32 word = geoI[blk * 4 + (tid >> 2)];
        sidx[tid] = (word >> ((tid & 3) * 8)) & 255u;
    }
    __syncthreads();
    int n = blk / 49;
    const __half* xb = x + ((size_t)(n >> 6) << 18);
    int c = tid * 8;
    __half2 a0 = __float2half2_rn(0.f), a1 = a0, a2 = a0, a3 = a0;
    #pragma unroll
    for (int t = 0; t < 16; t++) {
        __half2 w2 = *reinterpret_cast<const __half2*>(&sw[t]);
        uint4 hv = *(const uint4*)(xb + (sidx[t] << 10) + c);
        a0 = __hfma2(*reinterpret_cast<__half2*>(&hv.x), w2, a0);
        a1 = __hfma2(*reinterpret_cast<__half2*>(&hv.y), w2, a1);
        a2 = __hfma2(*reinterpret_cast<__half2*>(&hv.z), w2, a2);
        a3 = __hfma2(*reinterpret_cast<__half2*>(&hv.w), w2, a3);
    }
    uint4 outv;
    outv.x = *reinterpret_cast<u32*>(&a0);
    outv.y = *reinterpret_cast<u32*>(&a1);
    outv.z = *reinterpret_cast<u32*>(&a2);
    outv.w = *reinterpret_cast<u32*>(&a3);
    *(uint4*)(oh + ((size_t)blk << 10) + c) = outv;
}

// merged small preps: g2_w->w2h, g3_w->w3h, g1 rearrange, g1b pad, tb fold
__global__ void prep_misc(const float* __restrict__ g2w, const float* __restrict__ g3w,
                          const float* __restrict__ g1w, const float* __restrict__ g1b,
                          const float* __restrict__ cb, const float* __restrict__ bg,
                          const float* __restrict__ bb, const float* __restrict__ bm,
                          const float* __restrict__ bv,
                          __half* __restrict__ w2h, __half* __restrict__ w3h,
                          __half* __restrict__ g1H, float* __restrict__ g1b2,
                          float* __restrict__ tb)
{
    int blk = blockIdx.x;
    int tid = threadIdx.x;
    if (blk < 6400) {
        int i = blk * 256 + tid;
        w2h[i] = __float2half_rn(g2w[i]);
    } else if (blk < 12800) {
        int i = (blk - 6400) * 256 + tid;
        w3h[i] = __float2half_rn(g3w[i]);
    } else if (blk < 25600) {
        int i = (blk - 12800) * 256 + tid;   // < 2560*1280
        int n = i / 1280, k = i - n * 1280;
        int srcRow = (n >= 1280) ? (n - 1280) : n;
        int srcCol = ((n >= 1280) ? 1280 : 0) + k;
        g1H[i] = __float2half_rn(g1w[(size_t)srcRow * 2560 + srcCol]);
    } else if (blk < 25610) {
        int i = (blk - 25600) * 256 + tid;   // < 2560
        g1b2[i] = (i < 1280) ? g1b[i] : 0.f;
    } else {
        int o = tid;
        float s = bg[o] * rsqrtf(bv[o] + CEPS);
        tb[o] = (cb[o] - bm[o]) * s + bb[o];
    }
}

__global__ void prep_convw_fp16(const float* __restrict__ cw, const float* __restrict__ g,
                                const float* __restrict__ vv, __half* __restrict__ Wc) {
    __shared__ float sf[9216];
    int o = blockIdx.x;
    for (int j = threadIdx.x; j < 9216; j += 256) sf[j] = cw[o * 9216 + j];   // [ci][t]
    __syncthreads();
    float s = g[o] * rsqrtf(vv[o] + CEPS);
    for (int r = threadIdx.x; r < 9216; r += 256) {
        int t = r >> 10, ci = r & 1023;
        Wc[(size_t)o * 9216 + r] = __float2half_rn(sf[ci * 9 + t] * s);
    }
}

__global__ void prep_fcw(const float* __restrict__ fw, __half* __restrict__ o) {
    extern __shared__ float sf[];   // 12544 floats
    int n = blockIdx.x;
    for (int j = threadIdx.x; j < 12544; j += 256) sf[j] = fw[n * 12544 + j];
    __syncthreads();
    for (int j = threadIdx.x; j < 12544; j += 256) {
        int p = j >> 8, oo = j & 255;
        o[(size_t)n * 12544 + j] = __float2half_rn(sf[oo * 49 + p]);
    }
}

// conv split-K reduce: r1h = relu(P0 + P1 + tb)
__global__ void conv_reduce(const float* __restrict__ P, const float* __restrict__ tb,
                            __half* __restrict__ r1h) {
    int i = blockIdx.x * 256 + threadIdx.x;
    int e = i * 2;
    float2 a = *(const float2*)(P + e);
    float2 b = *(const float2*)(P + 25088ull * 256 + e);
    int col = e & 255;
    float v0 = fmaxf(a.x + b.x + tb[col], 0.f);
    float v1 = fmaxf(a.y + b.y + tb[col + 1], 0.f);
    *(u32*)(r1h + e) = h2_u32(v0, v1);
}

// ===================== HMMA GEMM: pure fp16, fp32 accum ====================
// 128x128 tile, 8 warps (2M x 4N, 64x32 each), K chunks of 64,
// 2-stage cp.async double buffer.
// MODE 0: g2 (A tile built on the fly: relu(U'+V) from UVh)
// MODE 1: g3   MODE 3: FC   MODE 4: proj   MODE 5: UV (+bias, fp16, ldc 2560)
// MODE 6: conv split-K (z over 2 halves of 144 chunks), raw f32 partials
template<int MODE>
__global__ void __launch_bounds__(256, 2) hgemm(
    const __half* __restrict__ A, const __half* __restrict__ B,
    const float* __restrict__ bias,
    __half* __restrict__ outH, float* __restrict__ outF,
    int nkin, int lda, int ldb)
{
    extern __shared__ char dsm[];
    const u32 raw = smem_u32(dsm);
    const u32 base = (raw + 1023u) & ~1023u;
    char* smem_g = dsm + (base - raw);

    const int tid = threadIdx.x;
    const int lane = tid & 31;
    const int w = tid >> 5;
    const int wM = w >> 2, wN = w & 3;
    const int nB = blockIdx.x * 128, mB = blockIdx.y * 128;
    const int kinBase = (MODE == 3 || MODE == 6) ? blockIdx.z * nkin : 0;

    const int lrow = tid >> 3, lc16 = tid & 7;

    int cn4[4], cy4[4], cx4[4];
    if (MODE == 6) {
        #pragma unroll
        for (int p = 0; p < 4; p++) {
            int r = mB + p * 32 + lrow;
            int n = r / 49, pp = r - n * 49;
            cn4[p] = n; cy4[p] = pp / 7; cx4[p] = pp - (pp / 7) * 7;
        }
    }
    int ru[4], rv[4];
    if (MODE == 0) {
        #pragma unroll
        for (int p = 0; p < 4; p++) {
            int row = mB + p * 32 + lrow;
            int img = row >> 12, a = (row >> 6) & 63, b = row & 63;
            ru[p] = img * 64 + b;
            rv[p] = img * 64 + a;
        }
    }

    u32 soff[4];
    #pragma unroll
    for (int p = 0; p < 4; p++) {
        u32 off = (u32)(((p * 32 + lrow) << 7) | (lc16 << 4));
        soff[p] = SWZ128(off);
    }

    auto gload = [&](int c, int s) {
        int kin = kinBase + c;
        u32 sg = base + (u32)s * 32768u;
        char* sgp = smem_g + (size_t)s * 32768u;
        int kOff = (kin << 6) + (lc16 << 3);
        if (MODE == 6) {
            int t = kin >> 4, ci0 = (kin & 15) << 6;
            int dy = t / 3 - 1, dx = t - (t / 3) * 3 - 1;
            #pragma unroll
            for (int p = 0; p < 4; p++) {
                int iy = cy4[p] + dy, ix = cx4[p] + dx;
                bool ok = (iy >= 0) && (iy < 7) && (ix >= 0) && (ix < 7);
                const __half* src = ok ?
                    (A + (((size_t)(cn4[p] * 49 + iy * 7 + ix)) << 10) + ci0 + (lc16 << 3)) : A;
                cpa16z(sg + soff[p], src, ok);
            }
        } else if (MODE == 0) {
            const __half2 z2 = __float2half2_rn(0.f);
            #pragma unroll
            for (int p = 0; p < 4; p++) {
                uint4 uv = *(const uint4*)(A + (size_t)ru[p] * 2560 + kOff);
                uint4 vv = *(const uint4*)(A + (size_t)rv[p] * 2560 + 1280 + kOff);
                const __half2* u2 = (const __half2*)&uv;
                const __half2* v2 = (const __half2*)&vv;
                uint4 r;
                __half2* r2 = (__half2*)&r;
                #pragma unroll
                for (int q = 0; q < 4; q++) r2[q] = __hmax2(__hadd2(u2[q], v2[q]), z2);
                *(uint4*)(sgp + soff[p]) = r;
            }
        } else {
            #pragma unroll
            for (int p = 0; p < 4; p++)
                cpa16(sg + soff[p], A + (size_t)(mB + p * 32 + lrow) * lda + kOff);
        }
        #pragma unroll
        for (int p = 0; p < 4; p++)
            cpa16(sg + 16384u + soff[p], B + (size_t)(nB + p * 32 + lrow) * ldb + kOff);
    };

    float acc[4][4][4];
    #pragma unroll
    for (int mi = 0; mi < 4; mi++)
        #pragma unroll
        for (int ni = 0; ni < 4; ni++)
            #pragma unroll
            for (int r = 0; r < 4; r++) acc[mi][ni][r] = 0.f;

    const u32 aRow = (u32)(wM * 64 + (lane & 15));
    const u32 aSegX = (lane & 16) ? 16u : 0u;
    const u32 bRow = (u32)(wN * 32 + (lane & 7) + ((lane & 16) ? 8 : 0));
    const u32 bSegX = (lane & 8) ? 16u : 0u;

    gload(0, 0); CP_COMMIT();
    if (nkin > 1) { gload(1, 1); CP_COMMIT(); }

    for (int c = 0; c < nkin; c++) {
        int s = c & 1;
        if (c + 1 < nkin) { CP_WAIT(1); } else { CP_WAIT(0); }
        __syncthreads();
        u32 aBase = base + (u32)s * 32768u;
        u32 bB = aBase + 16384u;
        #pragma unroll
        for (int ks = 0; ks < 4; ks++) {
            u32 kb = (u32)(ks * 32);
            u32 afr[4][4];
            #pragma unroll
            for (int mi = 0; mi < 4; mi++)
                ldsm4(afr[mi][0], afr[mi][1], afr[mi][2], afr[mi][3],
                      aBase + SWZ128(((aRow + mi * 16) << 7) + kb + aSegX));
            u32 bfr[4][2];
            #pragma unroll
            for (int q = 0; q < 2; q++) {
                u32 r0, r1, r2, r3;
                ldsm4(r0, r1, r2, r3, bB + SWZ128(((bRow + q * 16) << 7) + kb + bSegX));
                bfr[2 * q][0] = r0; bfr[2 * q][1] = r1;
                bfr[2 * q + 1][0] = r2; bfr[2 * q + 1][1] = r3;
            }
            #pragma unroll
            for (int mi = 0; mi < 4; mi++)
                #pragma unroll
                for (int ni = 0; ni < 4; ni++)
                    mma16816(acc[mi][ni], afr[mi], bfr[ni]);
        }
        __syncthreads();
        if (c + 2 < nkin) { gload(c + 2, s); CP_COMMIT(); }
    }

    // ---------------- epilogue ----------------
    const int gRow0 = mB + wM * 64 + (lane >> 2);
    const int gCol0 = nB + wN * 32 + (lane & 3) * 2;

    if (MODE == 0) {
        #pragma unroll
        for (int mi = 0; mi < 4; mi++)
            #pragma unroll
            for (int rg = 0; rg < 2; rg++) {
                int row = gRow0 + mi * 16 + rg * 8;
                #pragma unroll
                for (int ni = 0; ni < 4; ni++) {
                    int col = gCol0 + ni * 8;
                    float v0 = fmaxf(acc[mi][ni][rg * 2] + bias[col], 0.f);
                    float v1 = fmaxf(acc[mi][ni][rg * 2 + 1] + bias[col + 1], 0.f);
                    *(u32*)(outH + (size_t)row * 1280 + col) = h2_u32(v0, v1);
                }
            }
    } else if (MODE == 1) {
        float s0[4], s1[4];
        #pragma unroll
        for (int ni = 0; ni < 4; ni++) {
            int col = gCol0 + ni * 8;
            float b0 = bias[col], b1 = bias[col + 1];
            float t0 = 0.f, t1 = 0.f;
            #pragma unroll
            for (int mi = 0; mi < 4; mi++) {
                t0 += fmaxf(acc[mi][ni][0] + b0, 0.f) + fmaxf(acc[mi][ni][2] + b0, 0.f);
                t1 += fmaxf(acc[mi][ni][1] + b1, 0.f) + fmaxf(acc[mi][ni][3] + b1, 0.f);
            }
            #pragma unroll
            for (int m = 4; m < 32; m <<= 1) {
                t0 += __shfl_xor_sync(0xffffffffu, t0, m);
                t1 += __shfl_xor_sync(0xffffffffu, t1, m);
            }
            s0[ni] = t0; s1[ni] = t1;
        }
        float* CS = (float*)dsm;
        __syncthreads();
        if (lane < 4) {
            #pragma unroll
            for (int ni = 0; ni < 4; ni++) {
                int colL = wN * 32 + ni * 8 + lane * 2;
                CS[wM * 128 + colL] = s0[ni];
                CS[wM * 128 + colL + 1] = s1[ni];
            }
        }
        __syncthreads();
        if (tid < 128)
            outF[(size_t)blockIdx.y * 1280 + nB + tid] = CS[tid] + CS[128 + tid];
    } else if (MODE == 3) {
        float* Fout = outF + (size_t)blockIdx.z * 512 * 1024;
        #pragma unroll
        for (int mi = 0; mi < 4; mi++)
            #pragma unroll
            for (int rg = 0; rg < 2; rg++) {
                int row = gRow0 + mi * 16 + rg * 8;
                #pragma unroll
                for (int ni = 0; ni < 4; ni++) {
                    int col = gCol0 + ni * 8;
                    *(float2*)(Fout + (size_t)row * 1024 + col) =
                        make_float2(acc[mi][ni][rg * 2], acc[mi][ni][rg * 2 + 1]);
                }
            }
    } else if (MODE == 4) {
        #pragma unroll
        for (int mi = 0; mi < 4; mi++)
            #pragma unroll
            for (int rg = 0; rg < 2; rg++) {
                int row = gRow0 + mi * 16 + rg * 8;
                #pragma unroll
                for (int ni = 0; ni < 4; ni++) {
                    int col = gCol0 + ni * 8;
                    float v0 = acc[mi][ni][rg * 2] + bias[col];
                    float v1 = acc[mi][ni][rg * 2 + 1] + bias[col + 1];
                    *(u32*)(outH + (size_t)row * 1024 + col) = h2_u32(v0, v1);
                }
            }
    } else if (MODE == 5) {
        #pragma unroll
        for (int mi = 0; mi < 4; mi++)
            #pragma unroll
            for (int rg = 0; rg < 2; rg++) {
                int row = gRow0 + mi * 16 + rg * 8;
                #pragma unroll
                for (int ni = 0; ni < 4; ni++) {
                    int col = gCol0 + ni * 8;
                    float v0 = acc[mi][ni][rg * 2] + bias[col];
                    float v1 = acc[mi][ni][rg * 2 + 1] + bias[col + 1];
                    *(u32*)(outH + (size_t)row * 2560 + col) = h2_u32(v0, v1);
                }
            }
    } else {   // MODE 6: conv partials raw f32, ldc 256
        float* Fout = outF + (size_t)blockIdx.z * 25088 * 256;
        #pragma unroll
        for (int mi = 0; mi < 4; mi++)
            #pragma unroll
            for (int rg = 0; rg < 2; rg++) {
                int row = gRow0 + mi * 16 + rg * 8;
                #pragma unroll
                for (int ni = 0; ni < 4; ni++) {
                    int col = gCol0 + ni * 8;
                    *(float2*)(Fout + (size_t)row * 256 + col) =
                        make_float2(acc[mi][ni][rg * 2], acc[mi][ni][rg * 2 + 1]);
                }
            }
    }
}

// ===================== FC reduce + LN1 (fp16 out) =====================
__global__ void fc_reduce_ln(const float* __restrict__ part, const float* __restrict__ fcb,
                             const float* __restrict__ g, const float* __restrict__ b,
                             __half* __restrict__ featsH)
{
    __shared__ float sv[1024];
    __shared__ float red[256];
    int n = blockIdx.x, tid = threadIdx.x;
    float s = 0.f;
    #pragma unroll
    for (int i = 0; i < 4; i++) {
        int col = i * 256 + tid;
        float v = fcb[col];
        #pragma unroll
        for (int z = 0; z < 14; z++) v += part[(long long)((z << 9) + n) * 1024 + col];
        v = fmaxf(v, 0.f);
        sv[col] = v;
        s += v;
    }
    red[tid] = s; __syncthreads();
    for (int st = 128; st > 0; st >>= 1) { if (tid < st) red[tid] += red[tid + st]; __syncthreads(); }
    float mu = red[0] * (1.f / 1024.f);
    __syncthreads();
    float q = 0.f;
    #pragma unroll
    for (int i = 0; i < 4; i++) { float d = sv[i * 256 + tid] - mu; q += d * d; }
    red[tid] = q; __syncthreads();
    for (int st = 128; st > 0; st >>= 1) { if (tid < st) red[tid] += red[tid + st]; __syncthreads(); }
    float rstd = rsqrtf(red[0] * (1.f / 1024.f) + CEPS);
    #pragma unroll
    for (int i = 0; i < 4; i++) {
        int col = i * 256 + tid;
        featsH[(long long)n * 1280 + col] =
            __float2half_rn((sv[col] - mu) * rstd * g[col] + b[col]);
    }
}

// ===================== box branch (fp16 out) =====================
__global__ void box_ln(const float* __restrict__ nbx, const float* __restrict__ bw,
                       const float* __restrict__ bb, const float* __restrict__ g,
                       const float* __restrict__ be, __half* __restrict__ featsH)
{
    __shared__ float red[256];
    int n = blockIdx.x, tid = threadIdx.x;
    float a0 = nbx[n * 4 + 0] * 2.f - 1.f;
    float a1 = nbx[n * 4 + 1] * 2.f - 1.f;
    float a2 = nbx[n * 4 + 2] * 2.f - 1.f;
    float a3 = nbx[n * 4 + 3] * 2.f - 1.f;
    const float* w = bw + tid * 4;
    float v = w[0] * a0 + w[1] * a1 + w[2] * a2 + w[3] * a3 + bb[tid];
    red[tid] = v; __syncthreads();
    for (int st = 128; st > 0; st >>= 1) { if (tid < st) red[tid] += red[tid + st]; __syncthreads(); }
    float mu = red[0] * (1.f / 256.f);
    __syncthreads();
    float d = v - mu;
    red[tid] = d * d; __syncthreads();
    for (int st = 128; st > 0; st >>= 1) { if (tid < st) red[tid] += red[tid + st]; __syncthreads(); }
    float rstd = rsqrtf(red[0] * (1.f / 256.f) + CEPS);
    featsH[(long long)n * 1280 + 1024 + tid] =
        __float2half_rn((v - mu) * rstd * g[tid] + be[tid]);
}

// ===================== final reduce =====================
__global__ void final_reduce(const float* __restrict__ gp, float* __restrict__ out)
{
    int i = blockIdx.x * 256 + threadIdx.x;   // < 10240
    int img = i / 1280, j = i - img * 1280;
    float s = 0.f;
    #pragma unroll
    for (int mb = 0; mb < 32; mb++)
        s += gp[(long long)(img * 32 + mb) * 1280 + j];
    out[i] = s;
}

// ===================== launch =====================
extern "C" void kernel_launch(void* const* d_in, const int* in_sizes, int n_in,
                              void* d_out, int out_size)
{
    const float* im_feat = (const float*)d_in[0];
    const float* boxes   = (const float*)d_in[1];
    const float* nboxes  = (const float*)d_in[2];
    const float* proj_w  = (const float*)d_in[3];
    const float* proj_b  = (const float*)d_in[4];
    const float* conv_w  = (const float*)d_in[5];
    const float* conv_b  = (const float*)d_in[6];
    const float* bn_g = (const float*)d_in[7];
    const float* bn_b = (const float*)d_in[8];
    const float* bn_m = (const float*)d_in[9];
    const float* bn_v = (const float*)d_in[10];
    const float* fc_w = (const float*)d_in[11];
    const float* fc_b = (const float*)d_in[12];
    const float* ln1_g = (const float*)d_in[13];
    const float* ln1_b = (const float*)d_in[14];
    const float* box_w = (const float*)d_in[15];
    const float* box_b = (const float*)d_in[16];
    const float* ln2_g = (const float*)d_in[17];
    const float* ln2_b = (const float*)d_in[18];
    const float* g1_w = (const float*)d_in[19];
    const float* g1_b = (const float*)d_in[20];
    const float* g2_w = (const float*)d_in[21];
    const float* g2_b = (const float*)d_in[22];
    const float* g3_w = (const float*)d_in[23];
    const float* g3_b = (const float*)d_in[24];
    float* out = (float*)d_out;

    float *p_tb, *p_cvp, *p_fcp, *p_g1b2, *p_gp;
    u32 *p_geoW, *p_geoI;
    __half *p_imTh, *p_pwH, *p_xh, *p_Rh, *p_Wc, *p_r1h, *p_fcWh, *p_featsH, *p_g1H,
           *p_UVh, *p_h2h, *p_w2h, *p_w3h;
    cudaGetSymbolAddress((void**)&p_imTh, d_imTh);
    cudaGetSymbolAddress((void**)&p_pwH, d_pwH);
    cudaGetSymbolAddress((void**)&p_xh, d_xh);
    cudaGetSymbolAddress((void**)&p_tb, d_tb);
    cudaGetSymbolAddress((void**)&p_geoW, d_geoW);
    cudaGetSymbolAddress((void**)&p_geoI, d_geoI);
    cudaGetSymbolAddress((void**)&p_cvp, d_cvp);
    cudaGetSymbolAddress((void**)&p_fcp, d_fcp);
    cudaGetSymbolAddress((void**)&p_featsH, d_featsH);
    cudaGetSymbolAddress((void**)&p_g1H, d_g1H);
    cudaGetSymbolAddress((void**)&p_g1b2, d_g1b2);
    cudaGetSymbolAddress((void**)&p_UVh, d_UVh);
    cudaGetSymbolAddress((void**)&p_gp, d_gp);
    cudaGetSymbolAddress((void**)&p_Rh, d_Rh);
    cudaGetSymbolAddress((void**)&p_Wc, d_Wc);
    cudaGetSymbolAddress((void**)&p_r1h, d_r1h);
    cudaGetSymbolAddress((void**)&p_fcWh, d_fcWh);
    cudaGetSymbolAddress((void**)&p_h2h, d_h2h);
    cudaGetSymbolAddress((void**)&p_w2h, d_w2h);
    cudaGetSymbolAddress((void**)&p_w3h, d_w3h);

    const int SMEMSZ = 2 * 32768 + 1024;   // 66560
    cudaFuncSetAttribute(hgemm<0>, cudaFuncAttributeMaxDynamicSharedMemorySize, SMEMSZ);
    cudaFuncSetAttribute(hgemm<1>, cudaFuncAttributeMaxDynamicSharedMemorySize, SMEMSZ);
    cudaFuncSetAttribute(hgemm<3>, cudaFuncAttributeMaxDynamicSharedMemorySize, SMEMSZ);
    cudaFuncSetAttribute(hgemm<4>, cudaFuncAttributeMaxDynamicSharedMemorySize, SMEMSZ);
    cudaFuncSetAttribute(hgemm<5>, cudaFuncAttributeMaxDynamicSharedMemorySize, SMEMSZ);
    cudaFuncSetAttribute(hgemm<6>, cudaFuncAttributeMaxDynamicSharedMemorySize, SMEMSZ);
    cudaFuncSetAttribute(prep_fcw, cudaFuncAttributeMaxDynamicSharedMemorySize, 50176);

    roi_geom<<<98, 256>>>(boxes, p_geoW, p_geoI);                                 // 1
    transpose_bchw_h<<<dim3(8, 64, 8), dim3(32, 8)>>>(im_feat, p_imTh);          // 2
    conv_f2h<<<8192, 256>>>(proj_w, p_pwH, 1024 * 2048);                          // 3
    hgemm<4><<<dim3(8, 16), 256, SMEMSZ>>>(p_imTh, p_pwH, proj_b, p_xh, nullptr,  // 4
                                           32, 2048, 2048);
    roialign_gather<<<25088, 128>>>(p_xh, p_geoW, p_geoI, p_Rh);                  // 5
    prep_convw_fp16<<<256, 256>>>(conv_w, bn_g, bn_v, p_Wc);                      // 6
    prep_misc<<<25611, 256>>>(g2_w, g3_w, g1_w, g1_b, conv_b, bn_g, bn_b, bn_m,   // 7
                              bn_v, p_w2h, p_w3h, p_g1H, p_g1b2, p_tb);
    hgemm<6><<<dim3(2, 196, 2), 256, SMEMSZ>>>(p_Rh, p_Wc, nullptr, nullptr,      // 8
                                               p_cvp, 72, 0, 9216);
    conv_reduce<<<12544, 256>>>(p_cvp, p_tb, p_r1h);                              // 9
    prep_fcw<<<1024, 256, 50176>>>(fc_w, p_fcWh);                                 // 10
    hgemm<3><<<dim3(8, 4, 14), 256, SMEMSZ>>>(p_r1h, p_fcWh, nullptr, nullptr,    // 11
                                              p_fcp, 14, 12544, 12544);
    fc_reduce_ln<<<512, 256>>>(p_fcp, fc_b, ln1_g, ln1_b, p_featsH);              // 12
    box_ln<<<512, 256>>>(nboxes, box_w, box_b, ln2_g, ln2_b, p_featsH);           // 13
    hgemm<5><<<dim3(20, 4), 256, SMEMSZ>>>(p_featsH, p_g1H, p_g1b2, p_UVh,        // 14
                                           nullptr, 20, 1280, 1280);
    hgemm<0><<<dim3(10, 256), 256, SMEMSZ>>>(p_UVh, p_w2h, g2_b, p_h2h, nullptr,  // 15
                                             20, 2560, 1280);
    hgemm<1><<<dim3(10, 256), 256, SMEMSZ>>>(p_h2h, p_w3h, g3_b, nullptr, p_gp,   // 16
                                             20, 1280, 1280);
    final_reduce<<<40, 256>>>(p_gp, out);                                         // 17
}

// round 17
// speedup vs baseline: 1.0607x; 1.0222x over previous
#include <cuda_runtime.h>
#include <cuda_fp16.h>
#include <cstdint>

typedef unsigned long long u64;
typedef unsigned int u32;
#define CEPS 1e-5f

// ===================== helpers =====================
__device__ __forceinline__ u32 smem_u32(const void* p) {
    u32 a;
    asm("{ .reg .u64 t; cvta.to.shared.u64 t, %1; cvt.u32.u64 %0, t; }" : "=r"(a) : "l"(p));
    return a;
}
#define SWZ128(o) ((o) ^ (((o) >> 3) & 0x70))

__device__ __forceinline__ void ldsm4(u32& r0, u32& r1, u32& r2, u32& r3, u32 addr) {
    asm volatile("ldmatrix.sync.aligned.m8n8.x4.shared.b16 {%0,%1,%2,%3}, [%4];"
        : "=r"(r0), "=r"(r1), "=r"(r2), "=r"(r3) : "r"(addr));
}
__device__ __forceinline__ void mma16816(float* c, const u32* a, const u32* b) {
    asm volatile("mma.sync.aligned.m16n8k16.row.col.f32.f16.f16.f32 "
        "{%0,%1,%2,%3}, {%4,%5,%6,%7}, {%8,%9}, {%0,%1,%2,%3};"
        : "+f"(c[0]), "+f"(c[1]), "+f"(c[2]), "+f"(c[3])
        : "r"(a[0]), "r"(a[1]), "r"(a[2]), "r"(a[3]), "r"(b[0]), "r"(b[1]));
}
__device__ __forceinline__ void cpa16(u32 dst, const void* src) {
    asm volatile("cp.async.cg.shared.global [%0], [%1], 16;" :: "r"(dst), "l"(src));
}
__device__ __forceinline__ void cpa16z(u32 dst, const void* src, bool ok) {
    u32 sz = ok ? 16u : 0u;
    asm volatile("cp.async.cg.shared.global [%0], [%1], 16, %2;" :: "r"(dst), "l"(src), "r"(sz));
}
#define CP_COMMIT() asm volatile("cp.async.commit_group;" ::: "memory")
#define CP_WAIT(n)  asm volatile("cp.async.wait_group %0;" :: "n"(n) : "memory")

__device__ __forceinline__ u32 h2_u32(float a, float b) {
    __half2 h = __floats2half2_rn(a, b);
    return *reinterpret_cast<u32*>(&h);
}

// ===================== device scratch =====================
__device__ __half d_imTh[8 * 256 * 2048];         // [b][hw][cin] fp16
__device__ __half d_pwH[1024 * 2048];             // proj_w fp16
__device__ __half d_xh[8 * 256 * 1024];           // projected feats fp16
__device__ float d_tb[256];
__device__ u32 d_geoW[25088 * 16];                // per-(roi,bin) half2-splat weights
__device__ u32 d_geoI[25088 * 4];                 // per-(roi,bin) 16 packed u8 indices
__device__ __half d_Rh[512ull * 49 * 1024];       // roi feats fp16
__device__ __half d_Wc[256ull * 9216];            // conv w fp16 [o][t*1024+ci]
__device__ float d_cvp[2ull * 25088 * 256];       // conv split-K partials f32
__device__ __half d_r1h[512ull * 12544];          // conv out fp16, K order p*256+o
__device__ __half d_fcWh[1024ull * 12544];        // fc w fp16, K reordered
__device__ float d_fcp[14ull * 512 * 1024];       // FC split-K partials
__device__ __half d_featsH[512 * 1280];           // LN'd features fp16
__device__ __half d_g1H[2560 * 1280];             // g1 rearranged: [U rows | V rows][1280]
__device__ float d_g1b2[2560];                    // [g1_b | zeros]
__device__ __half d_UVh[512 * 2560];              // [row][U'(+bias) 1280 | V 1280] fp16
__device__ __half d_h2h[32768ull * 1280];
__device__ __half d_w2h[1280ull * 1280];
__device__ __half d_w3h[1280ull * 1280];
__device__ float d_gp[256 * 1280];

// ===================== prep kernels =====================
__global__ void transpose_bchw_h(const float* __restrict__ in, __half* __restrict__ out) {
    __shared__ float tile[32][33];
    int b = blockIdx.z, p0 = blockIdx.x * 32, c0 = blockIdx.y * 32;
    int tx = threadIdx.x, ty = threadIdx.y;
    const float* ip = in + (long long)b * 2048 * 256;
    #pragma unroll
    for (int i = 0; i < 32; i += 8) tile[ty + i][tx] = ip[(c0 + ty + i) * 256 + p0 + tx];
    __syncthreads();
    __half* op = out + (long long)b * 256 * 2048;
    #pragma unroll
    for (int i = 0; i < 32; i += 8)
        op[(p0 + ty + i) * 2048 + c0 + tx] = __float2half_rn(tile[tx][ty + i]);
}

__global__ void conv_f2h(const float* __restrict__ in, __half* __restrict__ out, int n) {
    int i = blockIdx.x * 256 + threadIdx.x;
    if (i < n) out[i] = __float2half_rn(in[i]);
}

// ROIAlign geometry: one thread per (roi, bin)
__global__ void roi_geom(const float* __restrict__ boxes,
                         u32* __restrict__ geoW, u32* __restrict__ geoI)
{
    int blk = blockIdx.x * 256 + threadIdx.x;
    if (blk >= 25088) return;
    int n = blk / 49;
    int bin = blk - n * 49;
    int by = bin / 7, bx = bin - by * 7;
    const float* roi = boxes + n * 4;
    float x1 = roi[0] * (1.f / 32.f) - 0.5f;
    float y1 = roi[1] * (1.f / 32.f) - 0.5f;
    float bw = (roi[2] - roi[0]) * (1.f / 32.f) * (1.f / 7.f);
    float bh = (roi[3] - roi[1]) * (1.f / 32.f) * (1.f / 7.f);
    int pidx[16];
    float pw[16];
    int cnt = 0;
    #pragma unroll
    for (int sy = 0; sy < 2; sy++) {
        float ys = y1 + bh * ((float)by + (sy + 0.5f) * 0.5f);
        bool vy = (ys >= -1.f) && (ys <= 16.f);
        float v = fmaxf(ys, 0.f);
        int lo = (int)floorf(v);
        int yl, yh; float wy;
        if (lo >= 15) { yl = 15; yh = 15; wy = 0.f; }
        else { yl = lo; yh = lo + 1; wy = v - (float)lo; }
        #pragma unroll
        for (int sx = 0; sx < 2; sx++) {
            float xs = x1 + bw * ((float)bx + (sx + 0.5f) * 0.5f);
            bool vx = (xs >= -1.f) && (xs <= 16.f);
            float u = fmaxf(xs, 0.f);
            int lo2 = (int)floorf(u);
            int xl, xh; float wx;
            if (lo2 >= 15) { xl = 15; xh = 15; wx = 0.f; }
            else { xl = lo2; xh = lo2 + 1; wx = u - (float)lo2; }
            float m = (vy && vx) ? 0.25f : 0.f;
            pidx[cnt] = yl * 16 + xl; pw[cnt] = (1.f - wy) * (1.f - wx) * m; cnt++;
            pidx[cnt] = yl * 16 + xh; pw[cnt] = (1.f - wy) * wx * m;         cnt++;
            pidx[cnt] = yh * 16 + xl; pw[cnt] = wy * (1.f - wx) * m;         cnt++;
            pidx[cnt] = yh * 16 + xh; pw[cnt] = wy * wx * m;                 cnt++;
        }
    }
    #pragma unroll
    for (int t = 0; t < 16; t++) {
        __half h = __float2half_rn(pw[t]);
        u32 hb = (u32)__half_as_ushort(h);
        geoW[blk * 16 + t] = hb | (hb << 16);
    }
    #pragma unroll
    for (int q = 0; q < 4; q++) {
        geoI[blk * 4 + q] = (u32)pidx[4 * q] | ((u32)pidx[4 * q + 1] << 8) |
                            ((u32)pidx[4 * q + 2] << 16) | ((u32)pidx[4 * q + 3] << 24);
    }
}

// ROIAlign gather: 128 threads x 8 channels, half2 accumulation
__global__ void __launch_bounds__(128) roialign_gather(
    const __half* __restrict__ x, const u32* __restrict__ geoW,
    const u32* __restrict__ geoI, __half* __restrict__ oh)
{
    __shared__ u32 sw[16];
    __shared__ u32 sidx[16];
    int blk = blockIdx.x;
    int tid = threadIdx.x;
    if (tid < 16) {
        sw[tid] = geoW[blk * 16 + tid];
        u32 word = geoI[blk * 4 + (tid >> 2)];
        sidx[tid] = (word >> ((tid & 3) * 8)) & 255u;
    }
    __syncthreads();
    int n = blk / 49;
    const __half* xb = x + ((size_t)(n >> 6) << 18);
    int c = tid * 8;
    __half2 a0 = __float2half2_rn(0.f), a1 = a0, a2 = a0, a3 = a0;
    #pragma unroll
    for (int t = 0; t < 16; t++) {
        __half2 w2 = *reinterpret_cast<const __half2*>(&sw[t]);
        uint4 hv = *(const uint4*)(xb + (sidx[t] << 10) + c);
        a0 = __hfma2(*reinterpret_cast<__half2*>(&hv.x), w2, a0);
        a1 = __hfma2(*reinterpret_cast<__half2*>(&hv.y), w2, a1);
        a2 = __hfma2(*reinterpret_cast<__half2*>(&hv.z), w2, a2);
        a3 = __hfma2(*reinterpret_cast<__half2*>(&hv.w), w2, a3);
    }
    uint4 outv;
    outv.x = *reinterpret_cast<u32*>(&a0);
    outv.y = *reinterpret_cast<u32*>(&a1);
    outv.z = *reinterpret_cast<u32*>(&a2);
    outv.w = *reinterpret_cast<u32*>(&a3);
    *(uint4*)(oh + ((size_t)blk << 10) + c) = outv;
}

// merged small preps: g2_w->w2h, g3_w->w3h, g1 rearrange, g1b pad, tb fold
__global__ void prep_misc(const float* __restrict__ g2w, const float* __restrict__ g3w,
                          const float* __restrict__ g1w, const float* __restrict__ g1b,
                          const float* __restrict__ cb, const float* __restrict__ bg,
                          const float* __restrict__ bb, const float* __restrict__ bm,
                          const float* __restrict__ bv,
                          __half* __restrict__ w2h, __half* __restrict__ w3h,
                          __half* __restrict__ g1H, float* __restrict__ g1b2,
                          float* __restrict__ tb)
{
    int blk = blockIdx.x;
    int tid = threadIdx.x;
    if (blk < 6400) {
        int i = blk * 256 + tid;
        w2h[i] = __float2half_rn(g2w[i]);
    } else if (blk < 12800) {
        int i = (blk - 6400) * 256 + tid;
        w3h[i] = __float2half_rn(g3w[i]);
    } else if (blk < 25600) {
        int i = (blk - 12800) * 256 + tid;   // < 2560*1280
        int n = i / 1280, k = i - n * 1280;
        int srcRow = (n >= 1280) ? (n - 1280) : n;
        int srcCol = ((n >= 1280) ? 1280 : 0) + k;
        g1H[i] = __float2half_rn(g1w[(size_t)srcRow * 2560 + srcCol]);
    } else if (blk < 25610) {
        int i = (blk - 25600) * 256 + tid;   // < 2560
        g1b2[i] = (i < 1280) ? g1b[i] : 0.f;
    } else {
        int o = tid;
        float s = bg[o] * rsqrtf(bv[o] + CEPS);
        tb[o] = (cb[o] - bm[o]) * s + bb[o];
    }
}

__global__ void prep_convw_fp16(const float* __restrict__ cw, const float* __restrict__ g,
                                const float* __restrict__ vv, __half* __restrict__ Wc) {
    __shared__ float sf[9216];
    int o = blockIdx.x;
    for (int j = threadIdx.x; j < 9216; j += 256) sf[j] = cw[o * 9216 + j];   // [ci][t]
    __syncthreads();
    float s = g[o] * rsqrtf(vv[o] + CEPS);
    for (int r = threadIdx.x; r < 9216; r += 256) {
        int t = r >> 10, ci = r & 1023;
        Wc[(size_t)o * 9216 + r] = __float2half_rn(sf[ci * 9 + t] * s);
    }
}

__global__ void prep_fcw(const float* __restrict__ fw, __half* __restrict__ o) {
    extern __shared__ float sf[];   // 12544 floats
    int n = blockIdx.x;
    for (int j = threadIdx.x; j < 12544; j += 256) sf[j] = fw[n * 12544 + j];
    __syncthreads();
    for (int j = threadIdx.x; j < 12544; j += 256) {
        int p = j >> 8, oo = j & 255;
        o[(size_t)n * 12544 + j] = __float2half_rn(sf[oo * 49 + p]);
    }
}

// conv split-K reduce: r1h = relu(P0 + P1 + tb)
__global__ void conv_reduce(const float* __restrict__ P, const float* __restrict__ tb,
                            __half* __restrict__ r1h) {
    int i = blockIdx.x * 256 + threadIdx.x;
    int e = i * 2;
    float2 a = *(const float2*)(P + e);
    float2 b = *(const float2*)(P + 25088ull * 256 + e);
    int col = e & 255;
    float v0 = fmaxf(a.x + b.x + tb[col], 0.f);
    float v1 = fmaxf(a.y + b.y + tb[col + 1], 0.f);
    *(u32*)(r1h + e) = h2_u32(v0, v1);
}

// ===================== HMMA GEMM: pure fp16, fp32 accum ====================
// 128x128 tile, 8 warps (2M x 4N, 64x32 each), K chunks of 64,
// 3-stage cp.async pipeline, ONE __syncthreads per chunk,
// body order = R8-proven (sync -> mma -> prefetch c+2).
// MODE 0: g2 (A tile built on the fly: relu(U'+V) from UVh)
// MODE 1: g3   MODE 3: FC   MODE 4: proj   MODE 5: UV (+bias, fp16, ldc 2560)
// MODE 6: conv split-K (z over 2 halves of 144 chunks), raw f32 partials
template<int MODE>
__global__ void __launch_bounds__(256, 2) hgemm(
    const __half* __restrict__ A, const __half* __restrict__ B,
    const float* __restrict__ bias,
    __half* __restrict__ outH, float* __restrict__ outF,
    int nkin, int lda, int ldb)
{
    extern __shared__ char dsm[];
    const u32 raw = smem_u32(dsm);
    const u32 base = (raw + 1023u) & ~1023u;
    char* smem_g = dsm + (base - raw);

    const int tid = threadIdx.x;
    const int lane = tid & 31;
    const int w = tid >> 5;
    const int wM = w >> 2, wN = w & 3;
    const int nB = blockIdx.x * 128, mB = blockIdx.y * 128;
    const int kinBase = (MODE == 3 || MODE == 6) ? blockIdx.z * nkin : 0;

    const int lrow = tid >> 3, lc16 = tid & 7;

    int cn4[4], cy4[4], cx4[4];
    if (MODE == 6) {
        #pragma unroll
        for (int p = 0; p < 4; p++) {
            int r = mB + p * 32 + lrow;
            int n = r / 49, pp = r - n * 49;
            cn4[p] = n; cy4[p] = pp / 7; cx4[p] = pp - (pp / 7) * 7;
        }
    }
    int ru[4], rv[4];
    if (MODE == 0) {
        #pragma unroll
        for (int p = 0; p < 4; p++) {
            int row = mB + p * 32 + lrow;
            int img = row >> 12, a = (row >> 6) & 63, b = row & 63;
            ru[p] = img * 64 + b;
            rv[p] = img * 64 + a;
        }
    }

    u32 soff[4];
    #pragma unroll
    for (int p = 0; p < 4; p++) {
        u32 off = (u32)(((p * 32 + lrow) << 7) | (lc16 << 4));
        soff[p] = SWZ128(off);
    }

    auto gload = [&](int c, int s) {
        int kin = kinBase + c;
        u32 sg = base + (u32)s * 32768u;
        char* sgp = smem_g + (size_t)s * 32768u;
        int kOff = (kin << 6) + (lc16 << 3);
        if (MODE == 6) {
            int t = kin >> 4, ci0 = (kin & 15) << 6;
            int dy = t / 3 - 1, dx = t - (t / 3) * 3 - 1;
            #pragma unroll
            for (int p = 0; p < 4; p++) {
                int iy = cy4[p] + dy, ix = cx4[p] + dx;
                bool ok = (iy >= 0) && (iy < 7) && (ix >= 0) && (ix < 7);
                const __half* src = ok ?
                    (A + (((size_t)(cn4[p] * 49 + iy * 7 + ix)) << 10) + ci0 + (lc16 << 3)) : A;
                cpa16z(sg + soff[p], src, ok);
            }
        } else if (MODE == 0) {
            const __half2 z2 = __float2half2_rn(0.f);
            #pragma unroll
            for (int p = 0; p < 4; p++) {
                uint4 uv = *(const uint4*)(A + (size_t)ru[p] * 2560 + kOff);
                uint4 vv = *(const uint4*)(A + (size_t)rv[p] * 2560 + 1280 + kOff);
                const __half2* u2 = (const __half2*)&uv;
                const __half2* v2 = (const __half2*)&vv;
                uint4 r;
                __half2* r2 = (__half2*)&r;
                #pragma unroll
                for (int q = 0; q < 4; q++) r2[q] = __hmax2(__hadd2(u2[q], v2[q]), z2);
                *(uint4*)(sgp + soff[p]) = r;
            }
        } else {
            #pragma unroll
            for (int p = 0; p < 4; p++)
                cpa16(sg + soff[p], A + (size_t)(mB + p * 32 + lrow) * lda + kOff);
        }
        #pragma unroll
        for (int p = 0; p < 4; p++)
            cpa16(sg + 16384u + soff[p], B + (size_t)(nB + p * 32 + lrow) * ldb + kOff);
    };

    float acc[4][4][4];
    #pragma unroll
    for (int mi = 0; mi < 4; mi++)
        #pragma unroll
        for (int ni = 0; ni < 4; ni++)
            #pragma unroll
            for (int r = 0; r < 4; r++) acc[mi][ni][r] = 0.f;

    const u32 aRow = (u32)(wM * 64 + (lane & 15));
    const u32 aSegX = (lane & 16) ? 16u : 0u;
    const u32 bRow = (u32)(wN * 32 + (lane & 7) + ((lane & 16) ? 8 : 0));
    const u32 bSegX = (lane & 8) ? 16u : 0u;

    gload(0, 0); CP_COMMIT();
    if (nkin > 1) { gload(1, 1); CP_COMMIT(); }

    int st = 0, pf = 2;
    for (int c = 0; c < nkin; c++) {
        if (c + 1 < nkin) { CP_WAIT(1); } else { CP_WAIT(0); }
        __syncthreads();
        u32 aBase = base + (u32)st * 32768u;
        u32 bB = aBase + 16384u;
        #pragma unroll
        for (int ks = 0; ks < 4; ks++) {
            u32 kb = (u32)(ks * 32);
            u32 afr[4][4];
            #pragma unroll
            for (int mi = 0; mi < 4; mi++)
                ldsm4(afr[mi][0], afr[mi][1], afr[mi][2], afr[mi][3],
                      aBase + SWZ128(((aRow + mi * 16) << 7) + kb + aSegX));
            u32 bfr[4][2];
            #pragma unroll
            for (int q = 0; q < 2; q++) {
                u32 r0, r1, r2, r3;
                ldsm4(r0, r1, r2, r3, bB + SWZ128(((bRow + q * 16) << 7) + kb + bSegX));
                bfr[2 * q][0] = r0; bfr[2 * q][1] = r1;
                bfr[2 * q + 1][0] = r2; bfr[2 * q + 1][1] = r3;
            }
            #pragma unroll
            for (int mi = 0; mi < 4; mi++)
                #pragma unroll
                for (int ni = 0; ni < 4; ni++)
                    mma16816(acc[mi][ni], afr[mi], bfr[ni]);
        }
        if (c + 2 < nkin) { gload(c + 2, pf); CP_COMMIT(); }
        st = (st == 2) ? 0 : st + 1;
        pf = (pf == 2) ? 0 : pf + 1;
    }
    __syncthreads();

    // ---------------- epilogue ----------------
    const int gRow0 = mB + wM * 64 + (lane >> 2);
    const int gCol0 = nB + wN * 32 + (lane & 3) * 2;

    if (MODE == 0) {
        #pragma unroll
        for (int mi = 0; mi < 4; mi++)
            #pragma unroll
            for (int rg = 0; rg < 2; rg++) {
                int row = gRow0 + mi * 16 + rg * 8;
                #pragma unroll
                for (int ni = 0; ni < 4; ni++) {
                    int col = gCol0 + ni * 8;
                    float v0 = fmaxf(acc[mi][ni][rg * 2] + bias[col], 0.f);
                    float v1 = fmaxf(acc[mi][ni][rg * 2 + 1] + bias[col + 1], 0.f);
                    *(u32*)(outH + (size_t)row * 1280 + col) = h2_u32(v0, v1);
                }
            }
    } else if (MODE == 1) {
        float s0[4], s1[4];
        #pragma unroll
        for (int ni = 0; ni < 4; ni++) {
            int col = gCol0 + ni * 8;
            float b0 = bias[col], b1 = bias[col + 1];
            float t0 = 0.f, t1 = 0.f;
            #pragma unroll
            for (int mi = 0; mi < 4; mi++) {
                t0 += fmaxf(acc[mi][ni][0] + b0, 0.f) + fmaxf(acc[mi][ni][2] + b0, 0.f);
                t1 += fmaxf(acc[mi][ni][1] + b1, 0.f) + fmaxf(acc[mi][ni][3] + b1, 0.f);
            }
            #pragma unroll
            for (int m = 4; m < 32; m <<= 1) {
                t0 += __shfl_xor_sync(0xffffffffu, t0, m);
                t1 += __shfl_xor_sync(0xffffffffu, t1, m);
            }
            s0[ni] = t0; s1[ni] = t1;
        }
        float* CS = (float*)dsm;
        __syncthreads();
        if (lane < 4) {
            #pragma unroll
            for (int ni = 0; ni < 4; ni++) {
                int colL = wN * 32 + ni * 8 + lane * 2;
                CS[wM * 128 + colL] = s0[ni];
                CS[wM * 128 + colL + 1] = s1[ni];
            }
        }
        __syncthreads();
        if (tid < 128)
            outF[(size_t)blockIdx.y * 1280 + nB + tid] = CS[tid] + CS[128 + tid];
    } else if (MODE == 3) {
        float* Fout = outF + (size_t)blockIdx.z * 512 * 1024;
        #pragma unroll
        for (int mi = 0; mi < 4; mi++)
            #pragma unroll
            for (int rg = 0; rg < 2; rg++) {
                int row = gRow0 + mi * 16 + rg * 8;
                #pragma unroll
                for (int ni = 0; ni < 4; ni++) {
                    int col = gCol0 + ni * 8;
                    *(float2*)(Fout + (size_t)row * 1024 + col) =
                        make_float2(acc[mi][ni][rg * 2], acc[mi][ni][rg * 2 + 1]);
                }
            }
    } else if (MODE == 4) {
        #pragma unroll
        for (int mi = 0; mi < 4; mi++)
            #pragma unroll
            for (int rg = 0; rg < 2; rg++) {
                int row = gRow0 + mi * 16 + rg * 8;
                #pragma unroll
                for (int ni = 0; ni < 4; ni++) {
                    int col = gCol0 + ni * 8;
                    float v0 = acc[mi][ni][rg * 2] + bias[col];
                    float v1 = acc[mi][ni][rg * 2 + 1] + bias[col + 1];
                    *(u32*)(outH + (size_t)row * 1024 + col) = h2_u32(v0, v1);
                }
            }
    } else if (MODE == 5) {
        #pragma unroll
        for (int mi = 0; mi < 4; mi++)
            #pragma unroll
            for (int rg = 0; rg < 2; rg++) {
                int row = gRow0 + mi * 16 + rg * 8;
                #pragma unroll
                for (int ni = 0; ni < 4; ni++) {
                    int col = gCol0 + ni * 8;
                    float v0 = acc[mi][ni][rg * 2] + bias[col];
                    float v1 = acc[mi][ni][rg * 2 + 1] + bias[col + 1];
                    *(u32*)(outH + (size_t)row * 2560 + col) = h2_u32(v0, v1);
                }
            }
    } else {   // MODE 6: conv partials raw f32, ldc 256
        float* Fout = outF + (size_t)blockIdx.z * 25088 * 256;
        #pragma unroll
        for (int mi = 0; mi < 4; mi++)
            #pragma unroll
            for (int rg = 0; rg < 2; rg++) {
                int row = gRow0 + mi * 16 + rg * 8;
                #pragma unroll
                for (int ni = 0; ni < 4; ni++) {
                    int col = gCol0 + ni * 8;
                    *(float2*)(Fout + (size_t)row * 256 + col) =
                        make_float2(acc[mi][ni][rg * 2], acc[mi][ni][rg * 2 + 1]);
                }
            }
    }
}

// ===================== FC reduce + LN1 (fp16 out) =====================
__global__ void fc_reduce_ln(const float* __restrict__ part, const float* __restrict__ fcb,
                             const float* __restrict__ g, const float* __restrict__ b,
                             __half* __restrict__ featsH)
{
    __shared__ float sv[1024];
    __shared__ float red[256];
    int n = blockIdx.x, tid = threadIdx.x;
    float s = 0.f;
    #pragma unroll
    for (int i = 0; i < 4; i++) {
        int col = i * 256 + tid;
        float v = fcb[col];
        #pragma unroll
        for (int z = 0; z < 14; z++) v += part[(long long)((z << 9) + n) * 1024 + col];
        v = fmaxf(v, 0.f);
        sv[col] = v;
        s += v;
    }
    red[tid] = s; __syncthreads();
    for (int st = 128; st > 0; st >>= 1) { if (tid < st) red[tid] += red[tid + st]; __syncthreads(); }
    float mu = red[0] * (1.f / 1024.f);
    __syncthreads();
    float q = 0.f;
    #pragma unroll
    for (int i = 0; i < 4; i++) { float d = sv[i * 256 + tid] - mu; q += d * d; }
    red[tid] = q; __syncthreads();
    for (int st = 128; st > 0; st >>= 1) { if (tid < st) red[tid] += red[tid + st]; __syncthreads(); }
    float rstd = rsqrtf(red[0] * (1.f / 1024.f) + CEPS);
    #pragma unroll
    for (int i = 0; i < 4; i++) {
        int col = i * 256 + tid;
        featsH[(long long)n * 1280 + col] =
            __float2half_rn((sv[col] - mu) * rstd * g[col] + b[col]);
    }
}

// ===================== box branch (fp16 out) =====================
__global__ void box_ln(const float* __restrict__ nbx, const float* __restrict__ bw,
                       const float* __restrict__ bb, const float* __restrict__ g,
                       const float* __restrict__ be, __half* __restrict__ featsH)
{
    __shared__ float red[256];
    int n = blockIdx.x, tid = threadIdx.x;
    float a0 = nbx[n * 4 + 0] * 2.f - 1.f;
    float a1 = nbx[n * 4 + 1] * 2.f - 1.f;
    float a2 = nbx[n * 4 + 2] * 2.f - 1.f;
    float a3 = nbx[n * 4 + 3] * 2.f - 1.f;
    const float* w = bw + tid * 4;
    float v = w[0] * a0 + w[1] * a1 + w[2] * a2 + w[3] * a3 + bb[tid];
    red[tid] = v; __syncthreads();
    for (int st = 128; st > 0; st >>= 1) { if (tid < st) red[tid] += red[tid + st]; __syncthreads(); }
    float mu = red[0] * (1.f / 256.f);
    __syncthreads();
    float d = v - mu;
    red[tid] = d * d; __syncthreads();
    for (int st = 128; st > 0; st >>= 1) { if (tid < st) red[tid] += red[tid + st]; __syncthreads(); }
    float rstd = rsqrtf(red[0] * (1.f / 256.f) + CEPS);
    featsH[(long long)n * 1280 + 1024 + tid] =
        __float2half_rn((v - mu) * rstd * g[tid] + be[tid]);
}

// ===================== final reduce =====================
__global__ void final_reduce(const float* __restrict__ gp, float* __restrict__ out)
{
    int i = blockIdx.x * 256 + threadIdx.x;   // < 10240
    int img = i / 1280, j = i - img * 1280;
    float s = 0.f;
    #pragma unroll
    for (int mb = 0; mb < 32; mb++)
        s += gp[(long long)(img * 32 + mb) * 1280 + j];
    out[i] = s;
}

// ===================== launch =====================
extern "C" void kernel_launch(void* const* d_in, const int* in_sizes, int n_in,
                              void* d_out, int out_size)
{
    const float* im_feat = (const float*)d_in[0];
    const float* boxes   = (const float*)d_in[1];
    const float* nboxes  = (const float*)d_in[2];
    const float* proj_w  = (const float*)d_in[3];
    const float* proj_b  = (const float*)d_in[4];
    const float* conv_w  = (const float*)d_in[5];
    const float* conv_b  = (const float*)d_in[6];
    const float* bn_g = (const float*)d_in[7];
    const float* bn_b = (const float*)d_in[8];
    const float* bn_m = (const float*)d_in[9];
    const float* bn_v = (const float*)d_in[10];
    const float* fc_w = (const float*)d_in[11];
    const float* fc_b = (const float*)d_in[12];
    const float* ln1_g = (const float*)d_in[13];
    const float* ln1_b = (const float*)d_in[14];
    const float* box_w = (const float*)d_in[15];
    const float* box_b = (const float*)d_in[16];
    const float* ln2_g = (const float*)d_in[17];
    const float* ln2_b = (const float*)d_in[18];
    const float* g1_w = (const float*)d_in[19];
    const float* g1_b = (const float*)d_in[20];
    const float* g2_w = (const float*)d_in[21];
    const float* g2_b = (const float*)d_in[22];
    const float* g3_w = (const float*)d_in[23];
    const float* g3_b = (const float*)d_in[24];
    float* out = (float*)d_out;

    float *p_tb, *p_cvp, *p_fcp, *p_g1b2, *p_gp;
    u32 *p_geoW, *p_geoI;
    __half *p_imTh, *p_pwH, *p_xh, *p_Rh, *p_Wc, *p_r1h, *p_fcWh, *p_featsH, *p_g1H,
           *p_UVh, *p_h2h, *p_w2h, *p_w3h;
    cudaGetSymbolAddress((void**)&p_imTh, d_imTh);
    cudaGetSymbolAddress((void**)&p_pwH, d_pwH);
    cudaGetSymbolAddress((void**)&p_xh, d_xh);
    cudaGetSymbolAddress((void**)&p_tb, d_tb);
    cudaGetSymbolAddress((void**)&p_geoW, d_geoW);
    cudaGetSymbolAddress((void**)&p_geoI, d_geoI);
    cudaGetSymbolAddress((void**)&p_cvp, d_cvp);
    cudaGetSymbolAddress((void**)&p_fcp, d_fcp);
    cudaGetSymbolAddress((void**)&p_featsH, d_featsH);
    cudaGetSymbolAddress((void**)&p_g1H, d_g1H);
    cudaGetSymbolAddress((void**)&p_g1b2, d_g1b2);
    cudaGetSymbolAddress((void**)&p_UVh, d_UVh);
    cudaGetSymbolAddress((void**)&p_gp, d_gp);
    cudaGetSymbolAddress((void**)&p_Rh, d_Rh);
    cudaGetSymbolAddress((void**)&p_Wc, d_Wc);
    cudaGetSymbolAddress((void**)&p_r1h, d_r1h);
    cudaGetSymbolAddress((void**)&p_fcWh, d_fcWh);
    cudaGetSymbolAddress((void**)&p_h2h, d_h2h);
    cudaGetSymbolAddress((void**)&p_w2h, d_w2h);
    cudaGetSymbolAddress((void**)&p_w3h, d_w3h);

    const int SMEMSZ = 3 * 32768 + 1024;   // 99328 (2 CTAs/SM: 194.6KB <= 228KB)
    cudaFuncSetAttribute(hgemm<0>, cudaFuncAttributeMaxDynamicSharedMemorySize, SMEMSZ);
    cudaFuncSetAttribute(hgemm<1>, cudaFuncAttributeMaxDynamicSharedMemorySize, SMEMSZ);
    cudaFuncSetAttribute(hgemm<3>, cudaFuncAttributeMaxDynamicSharedMemorySize, SMEMSZ);
    cudaFuncSetAttribute(hgemm<4>, cudaFuncAttributeMaxDynamicSharedMemorySize, SMEMSZ);
    cudaFuncSetAttribute(hgemm<5>, cudaFuncAttributeMaxDynamicSharedMemorySize, SMEMSZ);
    cudaFuncSetAttribute(hgemm<6>, cudaFuncAttributeMaxDynamicSharedMemorySize, SMEMSZ);
    cudaFuncSetAttribute(prep_fcw, cudaFuncAttributeMaxDynamicSharedMemorySize, 50176);

    roi_geom<<<98, 256>>>(boxes, p_geoW, p_geoI);                                 // 1
    transpose_bchw_h<<<dim3(8, 64, 8), dim3(32, 8)>>>(im_feat, p_imTh);          // 2
    conv_f2h<<<8192, 256>>>(proj_w, p_pwH, 1024 * 2048);                          // 3
    hgemm<4><<<dim3(8, 16), 256, SMEMSZ>>>(p_imTh, p_pwH, proj_b, p_xh, nullptr,  // 4
                                           32, 2048, 2048);
    roialign_gather<<<25088, 128>>>(p_xh, p_geoW, p_geoI, p_Rh);                  // 5
    prep_convw_fp16<<<256, 256>>>(conv_w, bn_g, bn_v, p_Wc);                      // 6
    prep_misc<<<25611, 256>>>(g2_w, g3_w, g1_w, g1_b, conv_b, bn_g, bn_b, bn_m,   // 7
                              bn_v, p_w2h, p_w3h, p_g1H, p_g1b2, p_tb);
    hgemm<6><<<dim3(2, 196, 2), 256, SMEMSZ>>>(p_Rh, p_Wc, nullptr, nullptr,      // 8
                                               p_cvp, 72, 0, 9216);
    conv_reduce<<<12544, 256>>>(p_cvp, p_tb, p_r1h);                              // 9
    prep_fcw<<<1024, 256, 50176>>>(fc_w, p_fcWh);                                 // 10
    hgemm<3><<<dim3(8, 4, 14), 256, SMEMSZ>>>(p_r1h, p_fcWh, nullptr, nullptr,    // 11
                                              p_fcp, 14, 12544, 12544);
    fc_reduce_ln<<<512, 256>>>(p_fcp, fc_b, ln1_g, ln1_b, p_featsH);              // 12
    box_ln<<<512, 256>>>(nboxes, box_w, box_b, ln2_g, ln2_b, p_featsH);           // 13
    hgemm<5><<<dim3(20, 4), 256, SMEMSZ>>>(p_featsH, p_g1H, p_g1b2, p_UVh,        // 14
                                           nullptr, 20, 1280, 1280);
    hgemm<0><<<dim3(10, 256), 256, SMEMSZ>>>(p_UVh, p_w2h, g2_b, p_h2h, nullptr,  // 15
                                             20, 2560, 1280);
    hgemm<1><<<dim3(10, 256), 256, SMEMSZ>>>(p_h2h, p_w3h, g3_b, nullptr, p_gp,   // 16
                                             20, 1280, 1280);
    final_reduce<<<40, 256>>>(p_gp, out);                                         // 17
}